// round 10
// baseline (speedup 1.0000x reference)
#include <cuda_runtime.h>
#include <cuda_fp16.h>
#include <math.h>
#include <stdint.h>

#define NROWS 16384
#define HDIM  1024
#define NEXP  6
#define NTASK 3
#define TOPK  3

typedef __half fp16;
#define NH_ ((long)NROWS * HDIM)          // 16777216
#define HH_ ((long)HDIM * HDIM)           // 1048576

// =============================== Scratch ===================================
__device__ __align__(256) fp16  g_cls[2 * NH_];
__device__ __align__(256) fp16  g_h1 [2 * NH_];
__device__ __align__(256) fp16  g_h  [2 * NH_];
__device__ __align__(256) fp16  g_eh [2 * NEXP * NH_];
__device__ __align__(256) float g_eo [NEXP * NH_];
__device__ __align__(256) fp16  g_mo [2 * NTASK * NH_];
__device__ __align__(256) float g_gates[(long)NTASK * NROWS * NEXP];
__device__ __align__(256) fp16  g_wt [34 * HH_];

// =============================== PTX helpers ===============================
__device__ __forceinline__ uint32_t smem_u32(const void* p) {
    uint32_t a;
    asm("{ .reg .u64 t; cvta.to.shared.u64 t, %1; cvt.u32.u64 %0, t; }" : "=r"(a) : "l"(p));
    return a;
}
__device__ __forceinline__ void cp16(uint32_t s, const void* g) {
    asm volatile("cp.async.cg.shared.global [%0], [%1], 16;" :: "r"(s), "l"(g) : "memory");
}
#define CP_COMMIT() asm volatile("cp.async.commit_group;" ::: "memory")
#define CP_WAIT1()  asm volatile("cp.async.wait_group 1;" ::: "memory")
#define CP_WAIT0()  asm volatile("cp.async.wait_group 0;" ::: "memory")

__device__ __forceinline__ void ldsm4(uint32_t (&r)[4], uint32_t addr) {
    asm volatile("ldmatrix.sync.aligned.m8n8.x4.shared.b16 {%0,%1,%2,%3}, [%4];"
                 : "=r"(r[0]), "=r"(r[1]), "=r"(r[2]), "=r"(r[3]) : "r"(addr));
}
__device__ __forceinline__ void mma_fp16(float (&d)[4], const uint32_t (&a)[4],
                                         uint32_t b0, uint32_t b1) {
    asm volatile(
        "mma.sync.aligned.m16n8k16.row.col.f32.f16.f16.f32 "
        "{%0,%1,%2,%3}, {%4,%5,%6,%7}, {%8,%9}, {%0,%1,%2,%3};"
        : "+f"(d[0]), "+f"(d[1]), "+f"(d[2]), "+f"(d[3])
        : "r"(a[0]), "r"(a[1]), "r"(a[2]), "r"(a[3]), "r"(b0), "r"(b1));
}

// ============================ split-fp16 GEMM ==============================
#define BM 128
#define BN 128
#define BK 32
#define NKCH (HDIM / BK)          // 32
#define MB_  8192                 // one 128x32 fp16 matrix, 64B rows
#define STG  (4 * MB_)            // 32768 per stage
#define SM_BYTES (3 * STG)        // 98304
#define GEMM_THREADS 128

__device__ __forceinline__ uint32_t swz(int row, int c16) {
    return (uint32_t)(row * 64 + ((c16 ^ ((row >> 1) & 3)) << 4));
}

template <bool RELU, bool WSPL, bool TOWER>
__global__ void __launch_bounds__(GEMM_THREADS, 2)
mma_gemm(const fp16* __restrict__ A0, const fp16* __restrict__ A1,
         const fp16* __restrict__ B0, const fp16* __restrict__ B1,
         const float* __restrict__ bias,
         float* __restrict__ Cf, fp16* __restrict__ C0, fp16* __restrict__ C1,
         const float* __restrict__ w2, float* __restrict__ outT,
         long sA, long sB, long sBias, long sC, long sW2)
{
    extern __shared__ char smem[];
    const uint32_t smbase = smem_u32(smem);
    const int tid = threadIdx.x, wid = tid >> 5, lane = tid & 31;
    const int z = blockIdx.z;
    const long row0 = (long)blockIdx.y * BM;
    const int  n0   = blockIdx.x * BN;

    const fp16* Ag0 = A0 + z * sA + row0 * HDIM;
    const fp16* Ag1 = A1 + z * sA + row0 * HDIM;
    const fp16* Bg0 = B0 + z * sB + (long)n0 * HDIM;
    const fp16* Bg1 = B1 + z * sB + (long)n0 * HDIM;

    const int ldr0 = tid >> 2, ldch = tid & 3;
    auto ldstage = [&](int buf, int kc0) {
        const uint32_t sb = smbase + buf * STG;
#pragma unroll
        for (int i = 0; i < 4; i++) {
            const int r = ldr0 + 32 * i;
            const long g = (long)r * HDIM + kc0 + ldch * 8;
            const uint32_t so = swz(r, ldch);
            cp16(sb + 0 * MB_ + so, Ag0 + g);
            cp16(sb + 1 * MB_ + so, Ag1 + g);
            cp16(sb + 2 * MB_ + so, Bg0 + g);
            cp16(sb + 3 * MB_ + so, Bg1 + g);
        }
    };

    float acc[4][8][4];
#pragma unroll
    for (int mt = 0; mt < 4; mt++)
#pragma unroll
        for (int nt = 0; nt < 8; nt++)
#pragma unroll
            for (int q = 0; q < 4; q++) acc[mt][nt][q] = 0.f;

    const int wm = (wid & 1) * 64;
    const int wn = (wid >> 1) * 64;
    const int grp = lane >> 3, lr = lane & 7;
    const int arow = lr + ((grp & 1) << 3);
    const int ac16 = grp >> 1;
    const int brow = lr + ((grp >> 1) << 3);
    const int bc16 = grp & 1;

    uint32_t abase[4], axm[4], bbase[4], bxm[4];
#pragma unroll
    for (int mt = 0; mt < 4; mt++) {
        const int r = wm + mt * 16 + arow;
        abase[mt] = (uint32_t)(r * 64);
        axm[mt]   = (uint32_t)((r >> 1) & 3);
    }
#pragma unroll
    for (int np = 0; np < 4; np++) {
        const int r = wn + np * 16 + brow;
        bbase[np] = (uint32_t)(r * 64);
        bxm[np]   = (uint32_t)((r >> 1) & 3);
    }

    ldstage(0, 0);           CP_COMMIT();
    ldstage(1, BK);          CP_COMMIT();

    for (int c = 0; c < NKCH; c++) {
        if (c + 1 < NKCH) CP_WAIT1(); else CP_WAIT0();
        __syncthreads();     // chunk c visible; buffer (c+2)%3 free

        // issue next-next chunk loads BEFORE compute: full chunk of latency
        if (c + 2 < NKCH) { ldstage((c + 2) % 3, (c + 2) * BK); CP_COMMIT(); }

        const uint32_t sb = smbase + (c % 3) * STG;
#pragma unroll
        for (int ks = 0; ks < 2; ks++) {
            const uint32_t ka = (uint32_t)(ks * 2 + ac16);
            const uint32_t kb = (uint32_t)(ks * 2 + bc16);
            uint32_t af[2][4][4];
            uint32_t bfr[2][4][4];

            // --- load hi fragments, then hh-term (hides ldsm latency) ---
#pragma unroll
            for (int mt = 0; mt < 4; mt++)
                ldsm4(af[0][mt], sb + 0 * MB_ + abase[mt] + ((ka ^ axm[mt]) << 4));
#pragma unroll
            for (int np = 0; np < 4; np++)
                ldsm4(bfr[0][np], sb + 2 * MB_ + bbase[np] + ((kb ^ bxm[np]) << 4));
#pragma unroll
            for (int np = 0; np < 4; np++)
#pragma unroll
                for (int mt = 0; mt < 4; mt++) {
                    mma_fp16(acc[mt][2 * np],     af[0][mt], bfr[0][np][0], bfr[0][np][1]);
                    mma_fp16(acc[mt][2 * np + 1], af[0][mt], bfr[0][np][2], bfr[0][np][3]);
                }

            // --- load A-lo, then lh-term ---
#pragma unroll
            for (int mt = 0; mt < 4; mt++)
                ldsm4(af[1][mt], sb + 1 * MB_ + abase[mt] + ((ka ^ axm[mt]) << 4));
#pragma unroll
            for (int np = 0; np < 4; np++)
#pragma unroll
                for (int mt = 0; mt < 4; mt++) {
                    mma_fp16(acc[mt][2 * np],     af[1][mt], bfr[0][np][0], bfr[0][np][1]);
                    mma_fp16(acc[mt][2 * np + 1], af[1][mt], bfr[0][np][2], bfr[0][np][3]);
                }

            // --- load B-lo, then hl-term ---
#pragma unroll
            for (int np = 0; np < 4; np++)
                ldsm4(bfr[1][np], sb + 3 * MB_ + bbase[np] + ((kb ^ bxm[np]) << 4));
#pragma unroll
            for (int np = 0; np < 4; np++)
#pragma unroll
                for (int mt = 0; mt < 4; mt++) {
                    mma_fp16(acc[mt][2 * np],     af[0][mt], bfr[1][np][0], bfr[1][np][1]);
                    mma_fp16(acc[mt][2 * np + 1], af[0][mt], bfr[1][np][2], bfr[1][np][3]);
                }
        }
    }

    // ------------------------------ epilogue ------------------------------
    const float* biasz = bias + z * sBias;
    const float* w2z   = TOWER ? (w2 + z * sW2) : nullptr;

#pragma unroll
    for (int mt = 0; mt < 4; mt++) {
#pragma unroll
        for (int half = 0; half < 2; half++) {
            const long gr = row0 + wm + mt * 16 + (lane >> 2) + half * 8;
            float p = 0.f;
#pragma unroll
            for (int nt = 0; nt < 8; nt++) {
                const int cc = n0 + wn + nt * 8 + (lane & 3) * 2;
                float v0 = acc[mt][nt][half * 2 + 0] + biasz[cc];
                float v1 = acc[mt][nt][half * 2 + 1] + biasz[cc + 1];
                if (RELU || TOWER) { v0 = fmaxf(v0, 0.f); v1 = fmaxf(v1, 0.f); }
                if (TOWER) {
                    p = fmaf(v0, w2z[cc], p);
                    p = fmaf(v1, w2z[cc + 1], p);
                } else {
                    const long off = z * sC + gr * HDIM + cc;
                    if (Cf != nullptr)
                        *reinterpret_cast<float2*>(&Cf[off]) = make_float2(v0, v1);
                    if (WSPL) {
                        fp16 h0 = __float2half_rn(v0), h1 = __float2half_rn(v1);
                        fp16 l0 = __float2half_rn(v0 - __half2float(h0));
                        fp16 l1 = __float2half_rn(v1 - __half2float(h1));
                        *reinterpret_cast<uint32_t*>(&C0[off]) =
                            (uint32_t)__half_as_ushort(h0) |
                            ((uint32_t)__half_as_ushort(h1) << 16);
                        *reinterpret_cast<uint32_t*>(&C1[off]) =
                            (uint32_t)__half_as_ushort(l0) |
                            ((uint32_t)__half_as_ushort(l1) << 16);
                    }
                }
            }
            if (TOWER) {
                p += __shfl_down_sync(0xffffffffu, p, 2);
                p += __shfl_down_sync(0xffffffffu, p, 1);
                if ((lane & 3) == 0)
                    atomicAdd(&outT[(long)z * NROWS + gr], p);
            }
        }
    }
}

// ======================= conversion / small kernels ========================
__global__ __launch_bounds__(256)
void cvt2_kernel(const float* __restrict__ in, fp16* __restrict__ c0,
                 fp16* __restrict__ c1, long n)
{
    const long i = (long)blockIdx.x * blockDim.x + threadIdx.x;
    if (i >= n) return;
    const float v = in[i];
    const fp16 h = __float2half_rn(v);
    c0[i] = h;
    c1[i] = __float2half_rn(v - __half2float(h));
}

// One kernel, all 17 weight units.
__global__ __launch_bounds__(256)
void transpose_all(const float* __restrict__ fc1w, const float* __restrict__ fc2w,
                   const float* __restrict__ ew1,  const float* __restrict__ ew2,
                   const float* __restrict__ tw1,  fp16* __restrict__ T)
{
    __shared__ float tile[32][33];
    const int z = blockIdx.z;
    const float* src;
    if      (z == 0)  src = fc1w;
    else if (z == 1)  src = fc2w;
    else if (z < 8)   src = ew1 + (long)(z - 2)  * HH_;
    else if (z < 14)  src = ew2 + (long)(z - 8)  * HH_;
    else              src = tw1 + (long)(z - 14) * HH_;
    const long ob = (long)z * 2 * HH_;
    const int k0 = blockIdx.y * 32, n0 = blockIdx.x * 32;
    for (int i = threadIdx.y; i < 32; i += 8)
        tile[i][threadIdx.x] = src[(long)(k0 + i) * HDIM + n0 + threadIdx.x];
    __syncthreads();
    for (int i = threadIdx.y; i < 32; i += 8) {
        const float v = tile[threadIdx.x][i];
        const fp16 h = __float2half_rn(v);
        const long o = ob + (long)(n0 + i) * HDIM + k0 + threadIdx.x;
        T[o] = h;
        T[o + HH_] = __float2half_rn(v - __half2float(h));
    }
}

// Gating (R8 version — known good): one warp per (t, n).
__global__ __launch_bounds__(256)
void gate_kernel(const fp16* __restrict__ h0, const fp16* __restrict__ h1,
                 const float* __restrict__ wg, float* __restrict__ gates)
{
    const int warp = (blockIdx.x * blockDim.x + threadIdx.x) >> 5;
    const int lane = threadIdx.x & 31;
    if (warp >= NTASK * NROWS) return;
    const int t = warp / NROWS;
    const int n = warp - t * NROWS;

    float acc[NEXP];
#pragma unroll
    for (int e = 0; e < NEXP; e++) acc[e] = 0.f;
    const fp16* hr0 = h0 + (long)n * HDIM;
    const fp16* hr1 = h1 + (long)n * HDIM;
    const float* wt = wg + (long)t * HDIM * NEXP;
    for (int hh = lane; hh < HDIM; hh += 32) {
        const float hv = __half2float(hr0[hh]) + __half2float(hr1[hh]);
        const float* wr = wt + (long)hh * NEXP;
#pragma unroll
        for (int e = 0; e < NEXP; e++) acc[e] = fmaf(hv, wr[e], acc[e]);
    }
#pragma unroll
    for (int off = 16; off > 0; off >>= 1)
#pragma unroll
        for (int e = 0; e < NEXP; e++)
            acc[e] += __shfl_xor_sync(0xffffffffu, acc[e], off);

    if (lane == 0) {
        float v[NEXP];
#pragma unroll
        for (int e = 0; e < NEXP; e++) v[e] = acc[e];
        int ti[TOPK]; float tv[TOPK];
#pragma unroll
        for (int s = 0; s < TOPK; s++) {
            int bi = 0; float bv = v[0];
#pragma unroll
            for (int e = 1; e < NEXP; e++) if (v[e] > bv) { bv = v[e]; bi = e; }
            ti[s] = bi; tv[s] = bv; v[bi] = -INFINITY;
        }
        const float m = tv[0];
        float w[TOPK], s = 0.f;
#pragma unroll
        for (int k = 0; k < TOPK; k++) { w[k] = expf(tv[k] - m); s += w[k]; }
        const float inv = 1.f / s;
        float gv[NEXP];
#pragma unroll
        for (int e = 0; e < NEXP; e++) gv[e] = 0.f;
#pragma unroll
        for (int k = 0; k < TOPK; k++) gv[ti[k]] = w[k] * inv;
        float* gp = gates + ((long)t * NROWS + n) * NEXP;
#pragma unroll
        for (int e = 0; e < NEXP; e++) gp[e] = gv[e];
    }
}

// mo[t] = sum_e gates[t,n,e]*eo[e,n,h], 4 elements per thread (vectorized)
__global__ __launch_bounds__(256)
void combine_kernel(const float* __restrict__ eo, const float* __restrict__ gates,
                    fp16* __restrict__ m0, fp16* __restrict__ m1)
{
    const long q = (long)blockIdx.x * blockDim.x + threadIdx.x;
    const long base = q * 4;
    if (base >= NH_) return;
    const int n = (int)(base >> 10);

    float4 v[NEXP];
#pragma unroll
    for (int e = 0; e < NEXP; e++)
        v[e] = *reinterpret_cast<const float4*>(eo + (long)e * NH_ + base);

#pragma unroll
    for (int t = 0; t < NTASK; t++) {
        const float* gp = gates + ((long)t * NROWS + n) * NEXP;
        float g[NEXP];
#pragma unroll
        for (int e = 0; e < NEXP; e++) g[e] = gp[e];
        float r[4] = {0.f, 0.f, 0.f, 0.f};
#pragma unroll
        for (int e = 0; e < NEXP; e++) {
            r[0] = fmaf(g[e], v[e].x, r[0]);
            r[1] = fmaf(g[e], v[e].y, r[1]);
            r[2] = fmaf(g[e], v[e].z, r[2]);
            r[3] = fmaf(g[e], v[e].w, r[3]);
        }
        uint2 hp, lp;
        {
            fp16 h0 = __float2half_rn(r[0]), h1 = __float2half_rn(r[1]);
            fp16 h2 = __float2half_rn(r[2]), h3 = __float2half_rn(r[3]);
            hp.x = (uint32_t)__half_as_ushort(h0) | ((uint32_t)__half_as_ushort(h1) << 16);
            hp.y = (uint32_t)__half_as_ushort(h2) | ((uint32_t)__half_as_ushort(h3) << 16);
            fp16 l0 = __float2half_rn(r[0] - __half2float(h0));
            fp16 l1 = __float2half_rn(r[1] - __half2float(h1));
            fp16 l2 = __float2half_rn(r[2] - __half2float(h2));
            fp16 l3 = __float2half_rn(r[3] - __half2float(h3));
            lp.x = (uint32_t)__half_as_ushort(l0) | ((uint32_t)__half_as_ushort(l1) << 16);
            lp.y = (uint32_t)__half_as_ushort(l2) | ((uint32_t)__half_as_ushort(l3) << 16);
        }
        *reinterpret_cast<uint2*>(m0 + (long)t * NH_ + base) = hp;
        *reinterpret_cast<uint2*>(m1 + (long)t * NH_ + base) = lp;
    }
}

__global__ void init_out_kernel(float* __restrict__ out, const float* __restrict__ tb2)
{
    const int i = blockIdx.x * blockDim.x + threadIdx.x;
    if (i < NTASK * NROWS) out[i] = tb2[i / NROWS];
}

// ================================ launch ===================================
extern "C" void kernel_launch(void* const* d_in, const int* in_sizes, int n_in,
                              void* d_out, int out_size)
{
    const float* cls   = (const float*)d_in[0];
    const float* fc1w  = (const float*)d_in[1];
    const float* fc1b  = (const float*)d_in[2];
    const float* fc2w  = (const float*)d_in[3];
    const float* fc2b  = (const float*)d_in[4];
    const float* wgate = (const float*)d_in[5];
    const float* ew1   = (const float*)d_in[6];
    const float* eb1   = (const float*)d_in[7];
    const float* ew2   = (const float*)d_in[8];
    const float* eb2   = (const float*)d_in[9];
    const float* tw1   = (const float*)d_in[10];
    const float* tb1   = (const float*)d_in[11];
    const float* tw2   = (const float*)d_in[12];
    const float* tb2   = (const float*)d_in[13];
    float* out = (float*)d_out;

    fp16 *clsS, *h1S, *hS, *ehS, *moS, *wt;
    float *eo, *gates;
    cudaGetSymbolAddress((void**)&clsS, g_cls);
    cudaGetSymbolAddress((void**)&h1S,  g_h1);
    cudaGetSymbolAddress((void**)&hS,   g_h);
    cudaGetSymbolAddress((void**)&ehS,  g_eh);
    cudaGetSymbolAddress((void**)&eo,   g_eo);
    cudaGetSymbolAddress((void**)&moS,  g_mo);
    cudaGetSymbolAddress((void**)&gates,g_gates);
    cudaGetSymbolAddress((void**)&wt,   g_wt);

    fp16* fc1t = wt;                 // unit 0
    fp16* fc2t = wt + 2 * HH_;       // unit 1
    fp16* ew1t = wt + 4 * HH_;       // units 2..7
    fp16* ew2t = wt + 16 * HH_;      // units 8..13
    fp16* tw1t = wt + 28 * HH_;      // units 14..16

    cudaFuncSetAttribute((const void*)mma_gemm<true,  true,  false>,
                         cudaFuncAttributeMaxDynamicSharedMemorySize, SM_BYTES);
    cudaFuncSetAttribute((const void*)mma_gemm<false, true,  false>,
                         cudaFuncAttributeMaxDynamicSharedMemorySize, SM_BYTES);
    cudaFuncSetAttribute((const void*)mma_gemm<false, false, false>,
                         cudaFuncAttributeMaxDynamicSharedMemorySize, SM_BYTES);
    cudaFuncSetAttribute((const void*)mma_gemm<false, false, true>,
                         cudaFuncAttributeMaxDynamicSharedMemorySize, SM_BYTES);

    const dim3 blk(256);
    const dim3 gblk(GEMM_THREADS);
    const dim3 tb(32, 8);
    const dim3 g1(HDIM / BN, NROWS / BM, 1);
    const dim3 gE(HDIM / BN, NROWS / BM, NEXP);
    const dim3 gT(HDIM / BN, NROWS / BM, NTASK);

    // 0: all 17 weight transposes
    transpose_all<<<dim3(32, 32, 17), tb>>>(fc1w, fc2w, ew1, ew2, tw1, wt);
    // 1: input split
    cvt2_kernel<<<(unsigned)(NH_ / 256), blk>>>(cls, clsS, clsS + NH_, NH_);

    // 2: fc1 (relu, split out)
    mma_gemm<true, true, false><<<g1, gblk, SM_BYTES>>>(
        clsS, clsS + NH_, fc1t, fc1t + HH_, fc1b,
        nullptr, h1S, h1S + NH_, nullptr, nullptr,
        0, 0, 0, 0, 0);
    // 3: fc2 (split out; gate reads comps)
    mma_gemm<false, true, false><<<g1, gblk, SM_BYTES>>>(
        h1S, h1S + NH_, fc2t, fc2t + HH_, fc2b,
        nullptr, hS, hS + NH_, nullptr, nullptr,
        0, 0, 0, 0, 0);

    // 4: gating
    gate_kernel<<<(NTASK * NROWS) / 8, blk>>>(hS, hS + NH_, wgate, gates);

    // 5: experts layer 1 (relu, split out)
    mma_gemm<true, true, false><<<gE, gblk, SM_BYTES>>>(
        hS, hS + NH_, ew1t, ew1t + HH_, eb1,
        nullptr, ehS, ehS + (long)NEXP * NH_, nullptr, nullptr,
        0, 2 * HH_, HDIM, NH_, 0);
    // 6: experts layer 2 (fp32 out)
    mma_gemm<false, false, false><<<gE, gblk, SM_BYTES>>>(
        ehS, ehS + (long)NEXP * NH_, ew2t, ew2t + HH_, eb2,
        eo, nullptr, nullptr, nullptr, nullptr,
        NH_, 2 * HH_, HDIM, NH_, 0);

    // 7: gate combine (vectorized x4)
    combine_kernel<<<(unsigned)(NH_ / 4 / 256), blk>>>(eo, gates, moS,
                                                       moS + (long)NTASK * NH_);

    // 8-9: towers (fused relu + tw2 reduction)
    init_out_kernel<<<(NTASK * NROWS + 255) / 256, blk>>>(out, tb2);
    mma_gemm<false, false, true><<<gT, gblk, SM_BYTES>>>(
        moS, moS + (long)NTASK * NH_, tw1t, tw1t + HH_, tb1,
        nullptr, nullptr, nullptr, tw2, out,
        NH_, 2 * HH_, HDIM, 0, HDIM);
}

// round 11
// speedup vs baseline: 1.0578x; 1.0578x over previous
#include <cuda_runtime.h>
#include <cuda_fp16.h>
#include <math.h>
#include <stdint.h>

#define NROWS 16384
#define HDIM  1024
#define NEXP  6
#define NTASK 3
#define TOPK  3

typedef __half fp16;
#define NH_ ((long)NROWS * HDIM)          // 16777216
#define HH_ ((long)HDIM * HDIM)           // 1048576

// =============================== Scratch ===================================
__device__ __align__(256) fp16  g_cls[2 * NH_];
__device__ __align__(256) fp16  g_h1 [2 * NH_];
__device__ __align__(256) fp16  g_h  [2 * NH_];
__device__ __align__(256) fp16  g_eh [2 * NEXP * NH_];
__device__ __align__(256) float g_eo [NEXP * NH_];
__device__ __align__(256) fp16  g_mo [2 * NTASK * NH_];
__device__ __align__(256) float g_gates[(long)NTASK * NROWS * NEXP];
__device__ __align__(256) fp16  g_wt [34 * HH_];

// =============================== PTX helpers ===============================
__device__ __forceinline__ uint32_t smem_u32(const void* p) {
    uint32_t a;
    asm("{ .reg .u64 t; cvta.to.shared.u64 t, %1; cvt.u32.u64 %0, t; }" : "=r"(a) : "l"(p));
    return a;
}
__device__ __forceinline__ void cp16(uint32_t s, const void* g) {
    asm volatile("cp.async.cg.shared.global [%0], [%1], 16;" :: "r"(s), "l"(g) : "memory");
}
#define CP_COMMIT() asm volatile("cp.async.commit_group;" ::: "memory")
#define CP_WAIT1()  asm volatile("cp.async.wait_group 1;" ::: "memory")
#define CP_WAIT0()  asm volatile("cp.async.wait_group 0;" ::: "memory")

__device__ __forceinline__ void ldsm4(uint32_t (&r)[4], uint32_t addr) {
    asm volatile("ldmatrix.sync.aligned.m8n8.x4.shared.b16 {%0,%1,%2,%3}, [%4];"
                 : "=r"(r[0]), "=r"(r[1]), "=r"(r[2]), "=r"(r[3]) : "r"(addr));
}
__device__ __forceinline__ void mma_fp16(float (&d)[4], const uint32_t (&a)[4],
                                         uint32_t b0, uint32_t b1) {
    asm volatile(
        "mma.sync.aligned.m16n8k16.row.col.f32.f16.f16.f32 "
        "{%0,%1,%2,%3}, {%4,%5,%6,%7}, {%8,%9}, {%0,%1,%2,%3};"
        : "+f"(d[0]), "+f"(d[1]), "+f"(d[2]), "+f"(d[3])
        : "r"(a[0]), "r"(a[1]), "r"(a[2]), "r"(a[3]), "r"(b0), "r"(b1));
}

// ============================ split-fp16 GEMM ==============================
// R8-proven loop: batched ldsm, term-major mma, ldstage AFTER compute.
#define BM 128
#define BN 128
#define BK 32
#define NKCH (HDIM / BK)          // 32
#define MB_  8192                 // one 128x32 fp16 matrix, 64B rows
#define STG  (4 * MB_)            // 32768 per stage
#define SM_BYTES (3 * STG)        // 98304
#define GEMM_THREADS 128

__device__ __forceinline__ uint32_t swz(int row, int c16) {
    return (uint32_t)(row * 64 + ((c16 ^ ((row >> 1) & 3)) << 4));
}

template <bool RELU, bool WSPL, bool TOWER>
__global__ void __launch_bounds__(GEMM_THREADS, 2)
mma_gemm(const fp16* __restrict__ A0, const fp16* __restrict__ A1,
         const fp16* __restrict__ B0, const fp16* __restrict__ B1,
         const float* __restrict__ bias,
         float* __restrict__ Cf, fp16* __restrict__ C0, fp16* __restrict__ C1,
         const float* __restrict__ w2, float* __restrict__ outT,
         long sA, long sB, long sBias, long sC, long sW2)
{
    extern __shared__ char smem[];
    const uint32_t smbase = smem_u32(smem);
    const int tid = threadIdx.x, wid = tid >> 5, lane = tid & 31;
    const int z = blockIdx.z;
    const long row0 = (long)blockIdx.y * BM;
    const int  n0   = blockIdx.x * BN;

    const fp16* Ag0 = A0 + z * sA + row0 * HDIM;
    const fp16* Ag1 = A1 + z * sA + row0 * HDIM;
    const fp16* Bg0 = B0 + z * sB + (long)n0 * HDIM;
    const fp16* Bg1 = B1 + z * sB + (long)n0 * HDIM;

    const int ldr0 = tid >> 2, ldch = tid & 3;
    auto ldstage = [&](int buf, int kc0) {
        const uint32_t sb = smbase + buf * STG;
#pragma unroll
        for (int i = 0; i < 4; i++) {
            const int r = ldr0 + 32 * i;
            const long g = (long)r * HDIM + kc0 + ldch * 8;
            const uint32_t so = swz(r, ldch);
            cp16(sb + 0 * MB_ + so, Ag0 + g);
            cp16(sb + 1 * MB_ + so, Ag1 + g);
            cp16(sb + 2 * MB_ + so, Bg0 + g);
            cp16(sb + 3 * MB_ + so, Bg1 + g);
        }
    };

    float acc[4][8][4];
#pragma unroll
    for (int mt = 0; mt < 4; mt++)
#pragma unroll
        for (int nt = 0; nt < 8; nt++)
#pragma unroll
            for (int q = 0; q < 4; q++) acc[mt][nt][q] = 0.f;

    const int wm = (wid & 1) * 64;
    const int wn = (wid >> 1) * 64;
    const int grp = lane >> 3, lr = lane & 7;
    const int arow = lr + ((grp & 1) << 3);
    const int ac16 = grp >> 1;
    const int brow = lr + ((grp >> 1) << 3);
    const int bc16 = grp & 1;

    uint32_t abase[4], axm[4], bbase[4], bxm[4];
#pragma unroll
    for (int mt = 0; mt < 4; mt++) {
        const int r = wm + mt * 16 + arow;
        abase[mt] = (uint32_t)(r * 64);
        axm[mt]   = (uint32_t)((r >> 1) & 3);
    }
#pragma unroll
    for (int np = 0; np < 4; np++) {
        const int r = wn + np * 16 + brow;
        bbase[np] = (uint32_t)(r * 64);
        bxm[np]   = (uint32_t)((r >> 1) & 3);
    }

    ldstage(0, 0);           CP_COMMIT();
    ldstage(1, BK);          CP_COMMIT();

    for (int c = 0; c < NKCH; c++) {
        if (c + 1 < NKCH) CP_WAIT1(); else CP_WAIT0();
        __syncthreads();     // chunk c published; buffer (c+2)%3 free

        const uint32_t sb = smbase + (c % 3) * STG;
#pragma unroll
        for (int ks = 0; ks < 2; ks++) {
            uint32_t af[2][4][4];
            uint32_t bfr[2][4][4];
            const uint32_t ka = (uint32_t)(ks * 2 + ac16);
            const uint32_t kb = (uint32_t)(ks * 2 + bc16);
#pragma unroll
            for (int sc = 0; sc < 2; sc++)
#pragma unroll
                for (int mt = 0; mt < 4; mt++)
                    ldsm4(af[sc][mt],
                          sb + sc * MB_ + abase[mt] + ((ka ^ axm[mt]) << 4));
#pragma unroll
            for (int sc = 0; sc < 2; sc++)
#pragma unroll
                for (int np = 0; np < 4; np++)
                    ldsm4(bfr[sc][np],
                          sb + (2 + sc) * MB_ + bbase[np] + ((kb ^ bxm[np]) << 4));

#pragma unroll
            for (int term = 0; term < 3; term++) {
                const int ai = (term == 2) ? 1 : 0;
                const int bi = (term == 1) ? 1 : 0;
#pragma unroll
                for (int np = 0; np < 4; np++)
#pragma unroll
                    for (int mt = 0; mt < 4; mt++) {
                        mma_fp16(acc[mt][2 * np],     af[ai][mt],
                                 bfr[bi][np][0], bfr[bi][np][1]);
                        mma_fp16(acc[mt][2 * np + 1], af[ai][mt],
                                 bfr[bi][np][2], bfr[bi][np][3]);
                    }
            }
        }

        if (c + 2 < NKCH) { ldstage((c + 2) % 3, (c + 2) * BK); CP_COMMIT(); }
    }

    // ------------------------------ epilogue ------------------------------
    const float* biasz = bias + z * sBias;
    const float* w2z   = TOWER ? (w2 + z * sW2) : nullptr;

#pragma unroll
    for (int mt = 0; mt < 4; mt++) {
#pragma unroll
        for (int half = 0; half < 2; half++) {
            const long gr = row0 + wm + mt * 16 + (lane >> 2) + half * 8;
            float p = 0.f;
#pragma unroll
            for (int nt = 0; nt < 8; nt++) {
                const int cc = n0 + wn + nt * 8 + (lane & 3) * 2;
                float v0 = acc[mt][nt][half * 2 + 0] + biasz[cc];
                float v1 = acc[mt][nt][half * 2 + 1] + biasz[cc + 1];
                if (RELU || TOWER) { v0 = fmaxf(v0, 0.f); v1 = fmaxf(v1, 0.f); }
                if (TOWER) {
                    p = fmaf(v0, w2z[cc], p);
                    p = fmaf(v1, w2z[cc + 1], p);
                } else {
                    const long off = z * sC + gr * HDIM + cc;
                    if (Cf != nullptr)
                        *reinterpret_cast<float2*>(&Cf[off]) = make_float2(v0, v1);
                    if (WSPL) {
                        fp16 h0 = __float2half_rn(v0), h1 = __float2half_rn(v1);
                        fp16 l0 = __float2half_rn(v0 - __half2float(h0));
                        fp16 l1 = __float2half_rn(v1 - __half2float(h1));
                        *reinterpret_cast<uint32_t*>(&C0[off]) =
                            (uint32_t)__half_as_ushort(h0) |
                            ((uint32_t)__half_as_ushort(h1) << 16);
                        *reinterpret_cast<uint32_t*>(&C1[off]) =
                            (uint32_t)__half_as_ushort(l0) |
                            ((uint32_t)__half_as_ushort(l1) << 16);
                    }
                }
            }
            if (TOWER) {
                p += __shfl_down_sync(0xffffffffu, p, 2);
                p += __shfl_down_sync(0xffffffffu, p, 1);
                if ((lane & 3) == 0)
                    atomicAdd(&outT[(long)z * NROWS + gr], p);
            }
        }
    }
}

// ======================= conversion / small kernels ========================
__global__ __launch_bounds__(256)
void cvt2_kernel(const float* __restrict__ in, fp16* __restrict__ c0,
                 fp16* __restrict__ c1, long n)
{
    const long i = (long)blockIdx.x * blockDim.x + threadIdx.x;
    if (i >= n) return;
    const float v = in[i];
    const fp16 h = __float2half_rn(v);
    c0[i] = h;
    c1[i] = __float2half_rn(v - __half2float(h));
}

// One kernel, all 17 weight units (R9-proven).
__global__ __launch_bounds__(256)
void transpose_all(const float* __restrict__ fc1w, const float* __restrict__ fc2w,
                   const float* __restrict__ ew1,  const float* __restrict__ ew2,
                   const float* __restrict__ tw1,  fp16* __restrict__ T)
{
    __shared__ float tile[32][33];
    const int z = blockIdx.z;
    const float* src;
    if      (z == 0)  src = fc1w;
    else if (z == 1)  src = fc2w;
    else if (z < 8)   src = ew1 + (long)(z - 2)  * HH_;
    else if (z < 14)  src = ew2 + (long)(z - 8)  * HH_;
    else              src = tw1 + (long)(z - 14) * HH_;
    const long ob = (long)z * 2 * HH_;
    const int k0 = blockIdx.y * 32, n0 = blockIdx.x * 32;
    for (int i = threadIdx.y; i < 32; i += 8)
        tile[i][threadIdx.x] = src[(long)(k0 + i) * HDIM + n0 + threadIdx.x];
    __syncthreads();
    for (int i = threadIdx.y; i < 32; i += 8) {
        const float v = tile[threadIdx.x][i];
        const fp16 h = __float2half_rn(v);
        const long o = ob + (long)(n0 + i) * HDIM + k0 + threadIdx.x;
        T[o] = h;
        T[o + HH_] = __float2half_rn(v - __half2float(h));
    }
}

// Gating (R8-proven): one warp per (t, n).
__global__ __launch_bounds__(256)
void gate_kernel(const fp16* __restrict__ h0, const fp16* __restrict__ h1,
                 const float* __restrict__ wg, float* __restrict__ gates)
{
    const int warp = (blockIdx.x * blockDim.x + threadIdx.x) >> 5;
    const int lane = threadIdx.x & 31;
    if (warp >= NTASK * NROWS) return;
    const int t = warp / NROWS;
    const int n = warp - t * NROWS;

    float acc[NEXP];
#pragma unroll
    for (int e = 0; e < NEXP; e++) acc[e] = 0.f;
    const fp16* hr0 = h0 + (long)n * HDIM;
    const fp16* hr1 = h1 + (long)n * HDIM;
    const float* wt = wg + (long)t * HDIM * NEXP;
    for (int hh = lane; hh < HDIM; hh += 32) {
        const float hv = __half2float(hr0[hh]) + __half2float(hr1[hh]);
        const float* wr = wt + (long)hh * NEXP;
#pragma unroll
        for (int e = 0; e < NEXP; e++) acc[e] = fmaf(hv, wr[e], acc[e]);
    }
#pragma unroll
    for (int off = 16; off > 0; off >>= 1)
#pragma unroll
        for (int e = 0; e < NEXP; e++)
            acc[e] += __shfl_xor_sync(0xffffffffu, acc[e], off);

    if (lane == 0) {
        float v[NEXP];
#pragma unroll
        for (int e = 0; e < NEXP; e++) v[e] = acc[e];
        int ti[TOPK]; float tv[TOPK];
#pragma unroll
        for (int s = 0; s < TOPK; s++) {
            int bi = 0; float bv = v[0];
#pragma unroll
            for (int e = 1; e < NEXP; e++) if (v[e] > bv) { bv = v[e]; bi = e; }
            ti[s] = bi; tv[s] = bv; v[bi] = -INFINITY;
        }
        const float m = tv[0];
        float w[TOPK], s = 0.f;
#pragma unroll
        for (int k = 0; k < TOPK; k++) { w[k] = expf(tv[k] - m); s += w[k]; }
        const float inv = 1.f / s;
        float gv[NEXP];
#pragma unroll
        for (int e = 0; e < NEXP; e++) gv[e] = 0.f;
#pragma unroll
        for (int k = 0; k < TOPK; k++) gv[ti[k]] = w[k] * inv;
        float* gp = gates + ((long)t * NROWS + n) * NEXP;
#pragma unroll
        for (int e = 0; e < NEXP; e++) gp[e] = gv[e];
    }
}

// Combine (R9-proven, vectorized x4)
__global__ __launch_bounds__(256)
void combine_kernel(const float* __restrict__ eo, const float* __restrict__ gates,
                    fp16* __restrict__ m0, fp16* __restrict__ m1)
{
    const long q = (long)blockIdx.x * blockDim.x + threadIdx.x;
    const long base = q * 4;
    if (base >= NH_) return;
    const int n = (int)(base >> 10);

    float4 v[NEXP];
#pragma unroll
    for (int e = 0; e < NEXP; e++)
        v[e] = *reinterpret_cast<const float4*>(eo + (long)e * NH_ + base);

#pragma unroll
    for (int t = 0; t < NTASK; t++) {
        const float* gp = gates + ((long)t * NROWS + n) * NEXP;
        float g[NEXP];
#pragma unroll
        for (int e = 0; e < NEXP; e++) g[e] = gp[e];
        float r[4] = {0.f, 0.f, 0.f, 0.f};
#pragma unroll
        for (int e = 0; e < NEXP; e++) {
            r[0] = fmaf(g[e], v[e].x, r[0]);
            r[1] = fmaf(g[e], v[e].y, r[1]);
            r[2] = fmaf(g[e], v[e].z, r[2]);
            r[3] = fmaf(g[e], v[e].w, r[3]);
        }
        uint2 hp, lp;
        {
            fp16 h0 = __float2half_rn(r[0]), h1 = __float2half_rn(r[1]);
            fp16 h2 = __float2half_rn(r[2]), h3 = __float2half_rn(r[3]);
            hp.x = (uint32_t)__half_as_ushort(h0) | ((uint32_t)__half_as_ushort(h1) << 16);
            hp.y = (uint32_t)__half_as_ushort(h2) | ((uint32_t)__half_as_ushort(h3) << 16);
            fp16 l0 = __float2half_rn(r[0] - __half2float(h0));
            fp16 l1 = __float2half_rn(r[1] - __half2float(h1));
            fp16 l2 = __float2half_rn(r[2] - __half2float(h2));
            fp16 l3 = __float2half_rn(r[3] - __half2float(h3));
            lp.x = (uint32_t)__half_as_ushort(l0) | ((uint32_t)__half_as_ushort(l1) << 16);
            lp.y = (uint32_t)__half_as_ushort(l2) | ((uint32_t)__half_as_ushort(l3) << 16);
        }
        *reinterpret_cast<uint2*>(m0 + (long)t * NH_ + base) = hp;
        *reinterpret_cast<uint2*>(m1 + (long)t * NH_ + base) = lp;
    }
}

__global__ void init_out_kernel(float* __restrict__ out, const float* __restrict__ tb2)
{
    const int i = blockIdx.x * blockDim.x + threadIdx.x;
    if (i < NTASK * NROWS) out[i] = tb2[i / NROWS];
}

// ================================ launch ===================================
extern "C" void kernel_launch(void* const* d_in, const int* in_sizes, int n_in,
                              void* d_out, int out_size)
{
    const float* cls   = (const float*)d_in[0];
    const float* fc1w  = (const float*)d_in[1];
    const float* fc1b  = (const float*)d_in[2];
    const float* fc2w  = (const float*)d_in[3];
    const float* fc2b  = (const float*)d_in[4];
    const float* wgate = (const float*)d_in[5];
    const float* ew1   = (const float*)d_in[6];
    const float* eb1   = (const float*)d_in[7];
    const float* ew2   = (const float*)d_in[8];
    const float* eb2   = (const float*)d_in[9];
    const float* tw1   = (const float*)d_in[10];
    const float* tb1   = (const float*)d_in[11];
    const float* tw2   = (const float*)d_in[12];
    const float* tb2   = (const float*)d_in[13];
    float* out = (float*)d_out;

    fp16 *clsS, *h1S, *hS, *ehS, *moS, *wt;
    float *eo, *gates;
    cudaGetSymbolAddress((void**)&clsS, g_cls);
    cudaGetSymbolAddress((void**)&h1S,  g_h1);
    cudaGetSymbolAddress((void**)&hS,   g_h);
    cudaGetSymbolAddress((void**)&ehS,  g_eh);
    cudaGetSymbolAddress((void**)&eo,   g_eo);
    cudaGetSymbolAddress((void**)&moS,  g_mo);
    cudaGetSymbolAddress((void**)&gates,g_gates);
    cudaGetSymbolAddress((void**)&wt,   g_wt);

    fp16* fc1t = wt;                 // unit 0
    fp16* fc2t = wt + 2 * HH_;       // unit 1
    fp16* ew1t = wt + 4 * HH_;       // units 2..7
    fp16* ew2t = wt + 16 * HH_;      // units 8..13
    fp16* tw1t = wt + 28 * HH_;      // units 14..16

    cudaFuncSetAttribute((const void*)mma_gemm<true,  true,  false>,
                         cudaFuncAttributeMaxDynamicSharedMemorySize, SM_BYTES);
    cudaFuncSetAttribute((const void*)mma_gemm<false, true,  false>,
                         cudaFuncAttributeMaxDynamicSharedMemorySize, SM_BYTES);
    cudaFuncSetAttribute((const void*)mma_gemm<false, false, false>,
                         cudaFuncAttributeMaxDynamicSharedMemorySize, SM_BYTES);
    cudaFuncSetAttribute((const void*)mma_gemm<false, false, true>,
                         cudaFuncAttributeMaxDynamicSharedMemorySize, SM_BYTES);

    const dim3 blk(256);
    const dim3 gblk(GEMM_THREADS);
    const dim3 tb(32, 8);
    const dim3 g1(HDIM / BN, NROWS / BM, 1);
    const dim3 gE(HDIM / BN, NROWS / BM, NEXP);
    const dim3 gT(HDIM / BN, NROWS / BM, NTASK);

    // 0: all 17 weight transposes
    transpose_all<<<dim3(32, 32, 17), tb>>>(fc1w, fc2w, ew1, ew2, tw1, wt);
    // 1: input split
    cvt2_kernel<<<(unsigned)(NH_ / 256), blk>>>(cls, clsS, clsS + NH_, NH_);

    // 2: fc1 (relu, split out)
    mma_gemm<true, true, false><<<g1, gblk, SM_BYTES>>>(
        clsS, clsS + NH_, fc1t, fc1t + HH_, fc1b,
        nullptr, h1S, h1S + NH_, nullptr, nullptr,
        0, 0, 0, 0, 0);
    // 3: fc2 (split out; gate reads comps)
    mma_gemm<false, true, false><<<g1, gblk, SM_BYTES>>>(
        h1S, h1S + NH_, fc2t, fc2t + HH_, fc2b,
        nullptr, hS, hS + NH_, nullptr, nullptr,
        0, 0, 0, 0, 0);

    // 4: gating
    gate_kernel<<<(NTASK * NROWS) / 8, blk>>>(hS, hS + NH_, wgate, gates);

    // 5: experts layer 1 (relu, split out)
    mma_gemm<true, true, false><<<gE, gblk, SM_BYTES>>>(
        hS, hS + NH_, ew1t, ew1t + HH_, eb1,
        nullptr, ehS, ehS + (long)NEXP * NH_, nullptr, nullptr,
        0, 2 * HH_, HDIM, NH_, 0);
    // 6: experts layer 2 (fp32 out)
    mma_gemm<false, false, false><<<gE, gblk, SM_BYTES>>>(
        ehS, ehS + (long)NEXP * NH_, ew2t, ew2t + HH_, eb2,
        eo, nullptr, nullptr, nullptr, nullptr,
        NH_, 2 * HH_, HDIM, NH_, 0);

    // 7: gate combine (vectorized x4)
    combine_kernel<<<(unsigned)(NH_ / 4 / 256), blk>>>(eo, gates, moS,
                                                       moS + (long)NTASK * NH_);

    // 8-9: towers (fused relu + tw2 reduction)
    init_out_kernel<<<(NTASK * NROWS + 255) / 256, blk>>>(out, tb2);
    mma_gemm<false, false, true><<<gT, gblk, SM_BYTES>>>(
        moS, moS + (long)NTASK * NH_, tw1t, tw1t + HH_, tb1,
        nullptr, nullptr, nullptr, tw2, out,
        NH_, 2 * HH_, HDIM, 0, HDIM);
}

// round 12
// speedup vs baseline: 1.0697x; 1.0112x over previous
#include <cuda_runtime.h>
#include <cuda_fp16.h>
#include <math.h>
#include <stdint.h>

#define NROWS 16384
#define HDIM  1024
#define NEXP  6
#define NTASK 3
#define TOPK  3

typedef __half fp16;
#define NH_ ((long)NROWS * HDIM)          // 16777216
#define HH_ ((long)HDIM * HDIM)           // 1048576

// =============================== Scratch ===================================
__device__ __align__(256) fp16  g_cls[2 * NH_];
__device__ __align__(256) fp16  g_h1 [2 * NH_];
__device__ __align__(256) fp16  g_h  [2 * NH_];
__device__ __align__(256) fp16  g_eh [2 * NEXP * NH_];
__device__ __align__(256) float g_eo [NEXP * NH_];
__device__ __align__(256) fp16  g_mo [2 * NTASK * NH_];
__device__ __align__(256) float g_gates[(long)NTASK * NROWS * NEXP];
__device__ __align__(256) fp16  g_wt [34 * HH_];

// =============================== PTX helpers ===============================
__device__ __forceinline__ uint32_t smem_u32(const void* p) {
    uint32_t a;
    asm("{ .reg .u64 t; cvta.to.shared.u64 t, %1; cvt.u32.u64 %0, t; }" : "=r"(a) : "l"(p));
    return a;
}
__device__ __forceinline__ void cp16(uint32_t s, const void* g) {
    asm volatile("cp.async.cg.shared.global [%0], [%1], 16;" :: "r"(s), "l"(g) : "memory");
}
#define CP_COMMIT() asm volatile("cp.async.commit_group;" ::: "memory")
#define CP_WAIT1()  asm volatile("cp.async.wait_group 1;" ::: "memory")
#define CP_WAIT0()  asm volatile("cp.async.wait_group 0;" ::: "memory")

__device__ __forceinline__ void ldsm4(uint32_t (&r)[4], uint32_t addr) {
    asm volatile("ldmatrix.sync.aligned.m8n8.x4.shared.b16 {%0,%1,%2,%3}, [%4];"
                 : "=r"(r[0]), "=r"(r[1]), "=r"(r[2]), "=r"(r[3]) : "r"(addr));
}
__device__ __forceinline__ void mma_fp16(float (&d)[4], const uint32_t (&a)[4],
                                         uint32_t b0, uint32_t b1) {
    asm volatile(
        "mma.sync.aligned.m16n8k16.row.col.f32.f16.f16.f32 "
        "{%0,%1,%2,%3}, {%4,%5,%6,%7}, {%8,%9}, {%0,%1,%2,%3};"
        : "+f"(d[0]), "+f"(d[1]), "+f"(d[2]), "+f"(d[3])
        : "r"(a[0]), "r"(a[1]), "r"(a[2]), "r"(a[3]), "r"(b0), "r"(b1));
}

// ============================ split-fp16 GEMM ==============================
// FROZEN R8/R11 loop: batched ldsm, term-major mma, ldstage AFTER compute.
#define BM 128
#define BN 128
#define BK 32
#define NKCH (HDIM / BK)          // 32
#define MB_  8192                 // one 128x32 fp16 matrix, 64B rows
#define STG  (4 * MB_)            // 32768 per stage
#define SM_BYTES (3 * STG)        // 98304
#define GEMM_THREADS 128

__device__ __forceinline__ uint32_t swz(int row, int c16) {
    return (uint32_t)(row * 64 + ((c16 ^ ((row >> 1) & 3)) << 4));
}

template <bool RELU, bool WSPL, bool TOWER>
__global__ void __launch_bounds__(GEMM_THREADS, 2)
mma_gemm(const fp16* __restrict__ A0, const fp16* __restrict__ A1,
         const fp16* __restrict__ B0, const fp16* __restrict__ B1,
         const float* __restrict__ bias,
         float* __restrict__ Cf, fp16* __restrict__ C0, fp16* __restrict__ C1,
         const float* __restrict__ w2, float* __restrict__ outT,
         long sA, long sB, long sBias, long sC, long sW2)
{
    extern __shared__ char smem[];
    const uint32_t smbase = smem_u32(smem);
    const int tid = threadIdx.x, wid = tid >> 5, lane = tid & 31;
    const int z = blockIdx.z;
    const long row0 = (long)blockIdx.y * BM;
    const int  n0   = blockIdx.x * BN;

    const fp16* Ag0 = A0 + z * sA + row0 * HDIM;
    const fp16* Ag1 = A1 + z * sA + row0 * HDIM;
    const fp16* Bg0 = B0 + z * sB + (long)n0 * HDIM;
    const fp16* Bg1 = B1 + z * sB + (long)n0 * HDIM;

    const int ldr0 = tid >> 2, ldch = tid & 3;
    auto ldstage = [&](int buf, int kc0) {
        const uint32_t sb = smbase + buf * STG;
#pragma unroll
        for (int i = 0; i < 4; i++) {
            const int r = ldr0 + 32 * i;
            const long g = (long)r * HDIM + kc0 + ldch * 8;
            const uint32_t so = swz(r, ldch);
            cp16(sb + 0 * MB_ + so, Ag0 + g);
            cp16(sb + 1 * MB_ + so, Ag1 + g);
            cp16(sb + 2 * MB_ + so, Bg0 + g);
            cp16(sb + 3 * MB_ + so, Bg1 + g);
        }
    };

    float acc[4][8][4];
#pragma unroll
    for (int mt = 0; mt < 4; mt++)
#pragma unroll
        for (int nt = 0; nt < 8; nt++)
#pragma unroll
            for (int q = 0; q < 4; q++) acc[mt][nt][q] = 0.f;

    const int wm = (wid & 1) * 64;
    const int wn = (wid >> 1) * 64;
    const int grp = lane >> 3, lr = lane & 7;
    const int arow = lr + ((grp & 1) << 3);
    const int ac16 = grp >> 1;
    const int brow = lr + ((grp >> 1) << 3);
    const int bc16 = grp & 1;

    uint32_t abase[4], axm[4], bbase[4], bxm[4];
#pragma unroll
    for (int mt = 0; mt < 4; mt++) {
        const int r = wm + mt * 16 + arow;
        abase[mt] = (uint32_t)(r * 64);
        axm[mt]   = (uint32_t)((r >> 1) & 3);
    }
#pragma unroll
    for (int np = 0; np < 4; np++) {
        const int r = wn + np * 16 + brow;
        bbase[np] = (uint32_t)(r * 64);
        bxm[np]   = (uint32_t)((r >> 1) & 3);
    }

    ldstage(0, 0);           CP_COMMIT();
    ldstage(1, BK);          CP_COMMIT();

    for (int c = 0; c < NKCH; c++) {
        if (c + 1 < NKCH) CP_WAIT1(); else CP_WAIT0();
        __syncthreads();     // chunk c published; buffer (c+2)%3 free

        const uint32_t sb = smbase + (c % 3) * STG;
#pragma unroll
        for (int ks = 0; ks < 2; ks++) {
            uint32_t af[2][4][4];
            uint32_t bfr[2][4][4];
            const uint32_t ka = (uint32_t)(ks * 2 + ac16);
            const uint32_t kb = (uint32_t)(ks * 2 + bc16);
#pragma unroll
            for (int sc = 0; sc < 2; sc++)
#pragma unroll
                for (int mt = 0; mt < 4; mt++)
                    ldsm4(af[sc][mt],
                          sb + sc * MB_ + abase[mt] + ((ka ^ axm[mt]) << 4));
#pragma unroll
            for (int sc = 0; sc < 2; sc++)
#pragma unroll
                for (int np = 0; np < 4; np++)
                    ldsm4(bfr[sc][np],
                          sb + (2 + sc) * MB_ + bbase[np] + ((kb ^ bxm[np]) << 4));

#pragma unroll
            for (int term = 0; term < 3; term++) {
                const int ai = (term == 2) ? 1 : 0;
                const int bi = (term == 1) ? 1 : 0;
#pragma unroll
                for (int np = 0; np < 4; np++)
#pragma unroll
                    for (int mt = 0; mt < 4; mt++) {
                        mma_fp16(acc[mt][2 * np],     af[ai][mt],
                                 bfr[bi][np][0], bfr[bi][np][1]);
                        mma_fp16(acc[mt][2 * np + 1], af[ai][mt],
                                 bfr[bi][np][2], bfr[bi][np][3]);
                    }
            }
        }

        if (c + 2 < NKCH) { ldstage((c + 2) % 3, (c + 2) * BK); CP_COMMIT(); }
    }

    // ------------------------------ epilogue ------------------------------
    const float* biasz = bias + z * sBias;
    const float* w2z   = TOWER ? (w2 + z * sW2) : nullptr;

#pragma unroll
    for (int mt = 0; mt < 4; mt++) {
#pragma unroll
        for (int half = 0; half < 2; half++) {
            const long gr = row0 + wm + mt * 16 + (lane >> 2) + half * 8;
            float p = 0.f;
#pragma unroll
            for (int nt = 0; nt < 8; nt++) {
                const int cc = n0 + wn + nt * 8 + (lane & 3) * 2;
                float v0 = acc[mt][nt][half * 2 + 0] + biasz[cc];
                float v1 = acc[mt][nt][half * 2 + 1] + biasz[cc + 1];
                if (RELU || TOWER) { v0 = fmaxf(v0, 0.f); v1 = fmaxf(v1, 0.f); }
                if (TOWER) {
                    p = fmaf(v0, w2z[cc], p);
                    p = fmaf(v1, w2z[cc + 1], p);
                } else {
                    const long off = z * sC + gr * HDIM + cc;
                    if (Cf != nullptr)
                        *reinterpret_cast<float2*>(&Cf[off]) = make_float2(v0, v1);
                    if (WSPL) {
                        fp16 h0 = __float2half_rn(v0), h1 = __float2half_rn(v1);
                        fp16 l0 = __float2half_rn(v0 - __half2float(h0));
                        fp16 l1 = __float2half_rn(v1 - __half2float(h1));
                        *reinterpret_cast<uint32_t*>(&C0[off]) =
                            (uint32_t)__half_as_ushort(h0) |
                            ((uint32_t)__half_as_ushort(h1) << 16);
                        *reinterpret_cast<uint32_t*>(&C1[off]) =
                            (uint32_t)__half_as_ushort(l0) |
                            ((uint32_t)__half_as_ushort(l1) << 16);
                    }
                }
            }
            if (TOWER) {
                p += __shfl_down_sync(0xffffffffu, p, 2);
                p += __shfl_down_sync(0xffffffffu, p, 1);
                if ((lane & 3) == 0)
                    atomicAdd(&outT[(long)z * NROWS + gr], p);
            }
        }
    }
}

// ===================== fused prep kernel (one launch) ======================
// blockIdx.x dispatch:
//   [0, 17408)            : transpose+split 17 weight units (32x32 tiles)
//   [17408, 17408+16384)  : cls fp32 -> fp16 hi/lo split (x4 vectorized)
//   [.., +192)            : out init to tb2[t]
#define TRN_BLOCKS  (17 * 1024)
#define CVT_BLOCKS  ((int)(NH_ / 4 / 256))          // 16384
#define INIT_BLOCKS ((NTASK * NROWS) / 256)         // 192
#define PREP_BLOCKS (TRN_BLOCKS + CVT_BLOCKS + INIT_BLOCKS)

__global__ __launch_bounds__(256)
void prep_kernel(const float* __restrict__ fc1w, const float* __restrict__ fc2w,
                 const float* __restrict__ ew1,  const float* __restrict__ ew2,
                 const float* __restrict__ tw1,  fp16* __restrict__ T,
                 const float* __restrict__ cls,  fp16* __restrict__ c0,
                 fp16* __restrict__ c1,
                 const float* __restrict__ tb2,  float* __restrict__ out)
{
    const int b = blockIdx.x;
    const int tid = threadIdx.x;

    if (b < TRN_BLOCKS) {
        __shared__ float tile[32][33];
        const int z   = b >> 10;
        const int rem = b & 1023;
        const int k0  = (rem >> 5) << 5;
        const int n0  = (rem & 31) << 5;
        const int tx  = tid & 31, ty = tid >> 5;
        const float* src;
        if      (z == 0)  src = fc1w;
        else if (z == 1)  src = fc2w;
        else if (z < 8)   src = ew1 + (long)(z - 2)  * HH_;
        else if (z < 14)  src = ew2 + (long)(z - 8)  * HH_;
        else              src = tw1 + (long)(z - 14) * HH_;
        const long ob = (long)z * 2 * HH_;
#pragma unroll
        for (int i = ty; i < 32; i += 8)
            tile[i][tx] = src[(long)(k0 + i) * HDIM + n0 + tx];
        __syncthreads();
#pragma unroll
        for (int i = ty; i < 32; i += 8) {
            const float v = tile[tx][i];
            const fp16 h = __float2half_rn(v);
            const long o = ob + (long)(n0 + i) * HDIM + k0 + tx;
            T[o] = h;
            T[o + HH_] = __float2half_rn(v - __half2float(h));
        }
    } else if (b < TRN_BLOCKS + CVT_BLOCKS) {
        const long base = ((long)(b - TRN_BLOCKS) * 256 + tid) * 4;
        const float4 v = *reinterpret_cast<const float4*>(cls + base);
        fp16 h0 = __float2half_rn(v.x), h1 = __float2half_rn(v.y);
        fp16 h2 = __float2half_rn(v.z), h3 = __float2half_rn(v.w);
        uint2 hp, lp;
        hp.x = (uint32_t)__half_as_ushort(h0) | ((uint32_t)__half_as_ushort(h1) << 16);
        hp.y = (uint32_t)__half_as_ushort(h2) | ((uint32_t)__half_as_ushort(h3) << 16);
        fp16 l0 = __float2half_rn(v.x - __half2float(h0));
        fp16 l1 = __float2half_rn(v.y - __half2float(h1));
        fp16 l2 = __float2half_rn(v.z - __half2float(h2));
        fp16 l3 = __float2half_rn(v.w - __half2float(h3));
        lp.x = (uint32_t)__half_as_ushort(l0) | ((uint32_t)__half_as_ushort(l1) << 16);
        lp.y = (uint32_t)__half_as_ushort(l2) | ((uint32_t)__half_as_ushort(l3) << 16);
        *reinterpret_cast<uint2*>(c0 + base) = hp;
        *reinterpret_cast<uint2*>(c1 + base) = lp;
    } else {
        const int i = (b - TRN_BLOCKS - CVT_BLOCKS) * 256 + tid;
        if (i < NTASK * NROWS) out[i] = tb2[i / NROWS];
    }
}

// Gating (R8-proven): one warp per (t, n).
__global__ __launch_bounds__(256)
void gate_kernel(const fp16* __restrict__ h0, const fp16* __restrict__ h1,
                 const float* __restrict__ wg, float* __restrict__ gates)
{
    const int warp = (blockIdx.x * blockDim.x + threadIdx.x) >> 5;
    const int lane = threadIdx.x & 31;
    if (warp >= NTASK * NROWS) return;
    const int t = warp / NROWS;
    const int n = warp - t * NROWS;

    float acc[NEXP];
#pragma unroll
    for (int e = 0; e < NEXP; e++) acc[e] = 0.f;
    const fp16* hr0 = h0 + (long)n * HDIM;
    const fp16* hr1 = h1 + (long)n * HDIM;
    const float* wt = wg + (long)t * HDIM * NEXP;
    for (int hh = lane; hh < HDIM; hh += 32) {
        const float hv = __half2float(hr0[hh]) + __half2float(hr1[hh]);
        const float* wr = wt + (long)hh * NEXP;
#pragma unroll
        for (int e = 0; e < NEXP; e++) acc[e] = fmaf(hv, wr[e], acc[e]);
    }
#pragma unroll
    for (int off = 16; off > 0; off >>= 1)
#pragma unroll
        for (int e = 0; e < NEXP; e++)
            acc[e] += __shfl_xor_sync(0xffffffffu, acc[e], off);

    if (lane == 0) {
        float v[NEXP];
#pragma unroll
        for (int e = 0; e < NEXP; e++) v[e] = acc[e];
        int ti[TOPK]; float tv[TOPK];
#pragma unroll
        for (int s = 0; s < TOPK; s++) {
            int bi = 0; float bv = v[0];
#pragma unroll
            for (int e = 1; e < NEXP; e++) if (v[e] > bv) { bv = v[e]; bi = e; }
            ti[s] = bi; tv[s] = bv; v[bi] = -INFINITY;
        }
        const float m = tv[0];
        float w[TOPK], s = 0.f;
#pragma unroll
        for (int k = 0; k < TOPK; k++) { w[k] = expf(tv[k] - m); s += w[k]; }
        const float inv = 1.f / s;
        float gv[NEXP];
#pragma unroll
        for (int e = 0; e < NEXP; e++) gv[e] = 0.f;
#pragma unroll
        for (int k = 0; k < TOPK; k++) gv[ti[k]] = w[k] * inv;
        float* gp = gates + ((long)t * NROWS + n) * NEXP;
#pragma unroll
        for (int e = 0; e < NEXP; e++) gp[e] = gv[e];
    }
}

// Combine (R9-proven, vectorized x4)
__global__ __launch_bounds__(256)
void combine_kernel(const float* __restrict__ eo, const float* __restrict__ gates,
                    fp16* __restrict__ m0, fp16* __restrict__ m1)
{
    const long q = (long)blockIdx.x * blockDim.x + threadIdx.x;
    const long base = q * 4;
    if (base >= NH_) return;
    const int n = (int)(base >> 10);

    float4 v[NEXP];
#pragma unroll
    for (int e = 0; e < NEXP; e++)
        v[e] = *reinterpret_cast<const float4*>(eo + (long)e * NH_ + base);

#pragma unroll
    for (int t = 0; t < NTASK; t++) {
        const float* gp = gates + ((long)t * NROWS + n) * NEXP;
        float g[NEXP];
#pragma unroll
        for (int e = 0; e < NEXP; e++) g[e] = gp[e];
        float r[4] = {0.f, 0.f, 0.f, 0.f};
#pragma unroll
        for (int e = 0; e < NEXP; e++) {
            r[0] = fmaf(g[e], v[e].x, r[0]);
            r[1] = fmaf(g[e], v[e].y, r[1]);
            r[2] = fmaf(g[e], v[e].z, r[2]);
            r[3] = fmaf(g[e], v[e].w, r[3]);
        }
        uint2 hp, lp;
        {
            fp16 h0 = __float2half_rn(r[0]), h1 = __float2half_rn(r[1]);
            fp16 h2 = __float2half_rn(r[2]), h3 = __float2half_rn(r[3]);
            hp.x = (uint32_t)__half_as_ushort(h0) | ((uint32_t)__half_as_ushort(h1) << 16);
            hp.y = (uint32_t)__half_as_ushort(h2) | ((uint32_t)__half_as_ushort(h3) << 16);
            fp16 l0 = __float2half_rn(r[0] - __half2float(h0));
            fp16 l1 = __float2half_rn(r[1] - __half2float(h1));
            fp16 l2 = __float2half_rn(r[2] - __half2float(h2));
            fp16 l3 = __float2half_rn(r[3] - __half2float(h3));
            lp.x = (uint32_t)__half_as_ushort(l0) | ((uint32_t)__half_as_ushort(l1) << 16);
            lp.y = (uint32_t)__half_as_ushort(l2) | ((uint32_t)__half_as_ushort(l3) << 16);
        }
        *reinterpret_cast<uint2*>(m0 + (long)t * NH_ + base) = hp;
        *reinterpret_cast<uint2*>(m1 + (long)t * NH_ + base) = lp;
    }
}

// ================================ launch ===================================
extern "C" void kernel_launch(void* const* d_in, const int* in_sizes, int n_in,
                              void* d_out, int out_size)
{
    const float* cls   = (const float*)d_in[0];
    const float* fc1w  = (const float*)d_in[1];
    const float* fc1b  = (const float*)d_in[2];
    const float* fc2w  = (const float*)d_in[3];
    const float* fc2b  = (const float*)d_in[4];
    const float* wgate = (const float*)d_in[5];
    const float* ew1   = (const float*)d_in[6];
    const float* eb1   = (const float*)d_in[7];
    const float* ew2   = (const float*)d_in[8];
    const float* eb2   = (const float*)d_in[9];
    const float* tw1   = (const float*)d_in[10];
    const float* tb1   = (const float*)d_in[11];
    const float* tw2   = (const float*)d_in[12];
    const float* tb2   = (const float*)d_in[13];
    float* out = (float*)d_out;

    fp16 *clsS, *h1S, *hS, *ehS, *moS, *wt;
    float *eo, *gates;
    cudaGetSymbolAddress((void**)&clsS, g_cls);
    cudaGetSymbolAddress((void**)&h1S,  g_h1);
    cudaGetSymbolAddress((void**)&hS,   g_h);
    cudaGetSymbolAddress((void**)&ehS,  g_eh);
    cudaGetSymbolAddress((void**)&eo,   g_eo);
    cudaGetSymbolAddress((void**)&moS,  g_mo);
    cudaGetSymbolAddress((void**)&gates,g_gates);
    cudaGetSymbolAddress((void**)&wt,   g_wt);

    fp16* fc1t = wt;                 // unit 0
    fp16* fc2t = wt + 2 * HH_;       // unit 1
    fp16* ew1t = wt + 4 * HH_;       // units 2..7
    fp16* ew2t = wt + 16 * HH_;      // units 8..13
    fp16* tw1t = wt + 28 * HH_;      // units 14..16

    cudaFuncSetAttribute((const void*)mma_gemm<true,  true,  false>,
                         cudaFuncAttributeMaxDynamicSharedMemorySize, SM_BYTES);
    cudaFuncSetAttribute((const void*)mma_gemm<false, true,  false>,
                         cudaFuncAttributeMaxDynamicSharedMemorySize, SM_BYTES);
    cudaFuncSetAttribute((const void*)mma_gemm<false, false, false>,
                         cudaFuncAttributeMaxDynamicSharedMemorySize, SM_BYTES);
    cudaFuncSetAttribute((const void*)mma_gemm<false, false, true>,
                         cudaFuncAttributeMaxDynamicSharedMemorySize, SM_BYTES);

    const dim3 blk(256);
    const dim3 gblk(GEMM_THREADS);
    const dim3 g1(HDIM / BN, NROWS / BM, 1);
    const dim3 gE(HDIM / BN, NROWS / BM, NEXP);
    const dim3 gT(HDIM / BN, NROWS / BM, NTASK);

    // 0: fused prep — weight transposes + input split + out init
    prep_kernel<<<PREP_BLOCKS, blk>>>(fc1w, fc2w, ew1, ew2, tw1, wt,
                                      cls, clsS, clsS + NH_, tb2, out);

    // 1: fc1 (relu, split out)
    mma_gemm<true, true, false><<<g1, gblk, SM_BYTES>>>(
        clsS, clsS + NH_, fc1t, fc1t + HH_, fc1b,
        nullptr, h1S, h1S + NH_, nullptr, nullptr,
        0, 0, 0, 0, 0);
    // 2: fc2 (split out; gate reads comps)
    mma_gemm<false, true, false><<<g1, gblk, SM_BYTES>>>(
        h1S, h1S + NH_, fc2t, fc2t + HH_, fc2b,
        nullptr, hS, hS + NH_, nullptr, nullptr,
        0, 0, 0, 0, 0);

    // 3: gating
    gate_kernel<<<(NTASK * NROWS) / 8, blk>>>(hS, hS + NH_, wgate, gates);

    // 4: experts layer 1 (relu, split out)
    mma_gemm<true, true, false><<<gE, gblk, SM_BYTES>>>(
        hS, hS + NH_, ew1t, ew1t + HH_, eb1,
        nullptr, ehS, ehS + (long)NEXP * NH_, nullptr, nullptr,
        0, 2 * HH_, HDIM, NH_, 0);
    // 5: experts layer 2 (fp32 out)
    mma_gemm<false, false, false><<<gE, gblk, SM_BYTES>>>(
        ehS, ehS + (long)NEXP * NH_, ew2t, ew2t + HH_, eb2,
        eo, nullptr, nullptr, nullptr, nullptr,
        NH_, 2 * HH_, HDIM, NH_, 0);

    // 6: gate combine (vectorized x4)
    combine_kernel<<<(unsigned)(NH_ / 4 / 256), blk>>>(eo, gates, moS,
                                                       moS + (long)NTASK * NH_);

    // 7: towers (fused relu + tw2 reduction; out pre-initialized by prep)
    mma_gemm<false, false, true><<<gT, gblk, SM_BYTES>>>(
        moS, moS + (long)NTASK * NH_, tw1t, tw1t + HH_, tb1,
        nullptr, nullptr, nullptr, tw2, out,
        NH_, 2 * HH_, HDIM, 0, HDIM);
}

// round 13
// speedup vs baseline: 1.0802x; 1.0098x over previous
#include <cuda_runtime.h>
#include <cuda_fp16.h>
#include <math.h>
#include <stdint.h>

#define NROWS 16384
#define HDIM  1024
#define NEXP  6
#define NTASK 3
#define TOPK  3

typedef __half fp16;
#define NH_ ((long)NROWS * HDIM)          // 16777216
#define HH_ ((long)HDIM * HDIM)           // 1048576

// =============================== Scratch ===================================
__device__ __align__(256) fp16  g_cls[2 * NH_];
__device__ __align__(256) fp16  g_h1 [2 * NH_];
__device__ __align__(256) fp16  g_h  [2 * NH_];
__device__ __align__(256) fp16  g_eh [2 * NEXP * NH_];
__device__ __align__(256) float g_eo [NEXP * NH_];
__device__ __align__(256) fp16  g_mo [2 * NTASK * NH_];
__device__ __align__(256) float g_gates[(long)NTASK * NROWS * NEXP];
__device__ __align__(256) fp16  g_wt [34 * HH_];
__device__ __align__(256) float g_wgt[NTASK * NEXP * HDIM];   // wgate^T [t][e][h]

// =============================== PTX helpers ===============================
__device__ __forceinline__ uint32_t smem_u32(const void* p) {
    uint32_t a;
    asm("{ .reg .u64 t; cvta.to.shared.u64 t, %1; cvt.u32.u64 %0, t; }" : "=r"(a) : "l"(p));
    return a;
}
__device__ __forceinline__ void cp16(uint32_t s, const void* g) {
    asm volatile("cp.async.cg.shared.global [%0], [%1], 16;" :: "r"(s), "l"(g) : "memory");
}
#define CP_COMMIT() asm volatile("cp.async.commit_group;" ::: "memory")
#define CP_WAIT1()  asm volatile("cp.async.wait_group 1;" ::: "memory")
#define CP_WAIT0()  asm volatile("cp.async.wait_group 0;" ::: "memory")

__device__ __forceinline__ void ldsm4(uint32_t (&r)[4], uint32_t addr) {
    asm volatile("ldmatrix.sync.aligned.m8n8.x4.shared.b16 {%0,%1,%2,%3}, [%4];"
                 : "=r"(r[0]), "=r"(r[1]), "=r"(r[2]), "=r"(r[3]) : "r"(addr));
}
__device__ __forceinline__ void mma_fp16(float (&d)[4], const uint32_t (&a)[4],
                                         uint32_t b0, uint32_t b1) {
    asm volatile(
        "mma.sync.aligned.m16n8k16.row.col.f32.f16.f16.f32 "
        "{%0,%1,%2,%3}, {%4,%5,%6,%7}, {%8,%9}, {%0,%1,%2,%3};"
        : "+f"(d[0]), "+f"(d[1]), "+f"(d[2]), "+f"(d[3])
        : "r"(a[0]), "r"(a[1]), "r"(a[2]), "r"(a[3]), "r"(b0), "r"(b1));
}

// ============================ split-fp16 GEMM ==============================
// FROZEN R8/R11 loop: batched ldsm, term-major mma, ldstage AFTER compute.
#define BM 128
#define BN 128
#define BK 32
#define NKCH (HDIM / BK)          // 32
#define MB_  8192                 // one 128x32 fp16 matrix, 64B rows
#define STG  (4 * MB_)            // 32768 per stage
#define SM_BYTES (3 * STG)        // 98304
#define GEMM_THREADS 128

__device__ __forceinline__ uint32_t swz(int row, int c16) {
    return (uint32_t)(row * 64 + ((c16 ^ ((row >> 1) & 3)) << 4));
}

template <bool RELU, bool WSPL, bool TOWER>
__global__ void __launch_bounds__(GEMM_THREADS, 2)
mma_gemm(const fp16* __restrict__ A0, const fp16* __restrict__ A1,
         const fp16* __restrict__ B0, const fp16* __restrict__ B1,
         const float* __restrict__ bias,
         float* __restrict__ Cf, fp16* __restrict__ C0, fp16* __restrict__ C1,
         const float* __restrict__ w2, float* __restrict__ outT,
         long sA, long sB, long sBias, long sC, long sW2)
{
    extern __shared__ char smem[];
    const uint32_t smbase = smem_u32(smem);
    const int tid = threadIdx.x, wid = tid >> 5, lane = tid & 31;
    const int z = blockIdx.z;
    const long row0 = (long)blockIdx.y * BM;
    const int  n0   = blockIdx.x * BN;

    const fp16* Ag0 = A0 + z * sA + row0 * HDIM;
    const fp16* Ag1 = A1 + z * sA + row0 * HDIM;
    const fp16* Bg0 = B0 + z * sB + (long)n0 * HDIM;
    const fp16* Bg1 = B1 + z * sB + (long)n0 * HDIM;

    const int ldr0 = tid >> 2, ldch = tid & 3;
    auto ldstage = [&](int buf, int kc0) {
        const uint32_t sb = smbase + buf * STG;
#pragma unroll
        for (int i = 0; i < 4; i++) {
            const int r = ldr0 + 32 * i;
            const long g = (long)r * HDIM + kc0 + ldch * 8;
            const uint32_t so = swz(r, ldch);
            cp16(sb + 0 * MB_ + so, Ag0 + g);
            cp16(sb + 1 * MB_ + so, Ag1 + g);
            cp16(sb + 2 * MB_ + so, Bg0 + g);
            cp16(sb + 3 * MB_ + so, Bg1 + g);
        }
    };

    float acc[4][8][4];
#pragma unroll
    for (int mt = 0; mt < 4; mt++)
#pragma unroll
        for (int nt = 0; nt < 8; nt++)
#pragma unroll
            for (int q = 0; q < 4; q++) acc[mt][nt][q] = 0.f;

    const int wm = (wid & 1) * 64;
    const int wn = (wid >> 1) * 64;
    const int grp = lane >> 3, lr = lane & 7;
    const int arow = lr + ((grp & 1) << 3);
    const int ac16 = grp >> 1;
    const int brow = lr + ((grp >> 1) << 3);
    const int bc16 = grp & 1;

    uint32_t abase[4], axm[4], bbase[4], bxm[4];
#pragma unroll
    for (int mt = 0; mt < 4; mt++) {
        const int r = wm + mt * 16 + arow;
        abase[mt] = (uint32_t)(r * 64);
        axm[mt]   = (uint32_t)((r >> 1) & 3);
    }
#pragma unroll
    for (int np = 0; np < 4; np++) {
        const int r = wn + np * 16 + brow;
        bbase[np] = (uint32_t)(r * 64);
        bxm[np]   = (uint32_t)((r >> 1) & 3);
    }

    ldstage(0, 0);           CP_COMMIT();
    ldstage(1, BK);          CP_COMMIT();

    for (int c = 0; c < NKCH; c++) {
        if (c + 1 < NKCH) CP_WAIT1(); else CP_WAIT0();
        __syncthreads();     // chunk c published; buffer (c+2)%3 free

        const uint32_t sb = smbase + (c % 3) * STG;
#pragma unroll
        for (int ks = 0; ks < 2; ks++) {
            uint32_t af[2][4][4];
            uint32_t bfr[2][4][4];
            const uint32_t ka = (uint32_t)(ks * 2 + ac16);
            const uint32_t kb = (uint32_t)(ks * 2 + bc16);
#pragma unroll
            for (int sc = 0; sc < 2; sc++)
#pragma unroll
                for (int mt = 0; mt < 4; mt++)
                    ldsm4(af[sc][mt],
                          sb + sc * MB_ + abase[mt] + ((ka ^ axm[mt]) << 4));
#pragma unroll
            for (int sc = 0; sc < 2; sc++)
#pragma unroll
                for (int np = 0; np < 4; np++)
                    ldsm4(bfr[sc][np],
                          sb + (2 + sc) * MB_ + bbase[np] + ((kb ^ bxm[np]) << 4));

#pragma unroll
            for (int term = 0; term < 3; term++) {
                const int ai = (term == 2) ? 1 : 0;
                const int bi = (term == 1) ? 1 : 0;
#pragma unroll
                for (int np = 0; np < 4; np++)
#pragma unroll
                    for (int mt = 0; mt < 4; mt++) {
                        mma_fp16(acc[mt][2 * np],     af[ai][mt],
                                 bfr[bi][np][0], bfr[bi][np][1]);
                        mma_fp16(acc[mt][2 * np + 1], af[ai][mt],
                                 bfr[bi][np][2], bfr[bi][np][3]);
                    }
            }
        }

        if (c + 2 < NKCH) { ldstage((c + 2) % 3, (c + 2) * BK); CP_COMMIT(); }
    }

    // ------------------------------ epilogue ------------------------------
    const float* biasz = bias + z * sBias;
    const float* w2z   = TOWER ? (w2 + z * sW2) : nullptr;

#pragma unroll
    for (int mt = 0; mt < 4; mt++) {
#pragma unroll
        for (int half = 0; half < 2; half++) {
            const long gr = row0 + wm + mt * 16 + (lane >> 2) + half * 8;
            float p = 0.f;
#pragma unroll
            for (int nt = 0; nt < 8; nt++) {
                const int cc = n0 + wn + nt * 8 + (lane & 3) * 2;
                float v0 = acc[mt][nt][half * 2 + 0] + biasz[cc];
                float v1 = acc[mt][nt][half * 2 + 1] + biasz[cc + 1];
                if (RELU || TOWER) { v0 = fmaxf(v0, 0.f); v1 = fmaxf(v1, 0.f); }
                if (TOWER) {
                    p = fmaf(v0, w2z[cc], p);
                    p = fmaf(v1, w2z[cc + 1], p);
                } else {
                    const long off = z * sC + gr * HDIM + cc;
                    if (Cf != nullptr)
                        *reinterpret_cast<float2*>(&Cf[off]) = make_float2(v0, v1);
                    if (WSPL) {
                        fp16 h0 = __float2half_rn(v0), h1 = __float2half_rn(v1);
                        fp16 l0 = __float2half_rn(v0 - __half2float(h0));
                        fp16 l1 = __float2half_rn(v1 - __half2float(h1));
                        *reinterpret_cast<uint32_t*>(&C0[off]) =
                            (uint32_t)__half_as_ushort(h0) |
                            ((uint32_t)__half_as_ushort(h1) << 16);
                        *reinterpret_cast<uint32_t*>(&C1[off]) =
                            (uint32_t)__half_as_ushort(l0) |
                            ((uint32_t)__half_as_ushort(l1) << 16);
                    }
                }
            }
            if (TOWER) {
                p += __shfl_down_sync(0xffffffffu, p, 2);
                p += __shfl_down_sync(0xffffffffu, p, 1);
                if ((lane & 3) == 0)
                    atomicAdd(&outT[(long)z * NROWS + gr], p);
            }
        }
    }
}

// ===================== fused prep kernel (one launch) ======================
// blockIdx.x dispatch:
//   [0, 17408)       : transpose+split 17 weight units (32x32 tiles)
//   [+16384)         : cls fp32 -> fp16 hi/lo split (x4 vectorized)
//   [+192)           : out init to tb2[t]
//   [+72)            : wgate transpose [t][h][e] -> [t][e][h]
#define TRN_BLOCKS  (17 * 1024)
#define CVT_BLOCKS  ((int)(NH_ / 4 / 256))          // 16384
#define INIT_BLOCKS ((NTASK * NROWS) / 256)         // 192
#define WGT_BLOCKS  ((NTASK * NEXP * HDIM) / 256)   // 72
#define PREP_BLOCKS (TRN_BLOCKS + CVT_BLOCKS + INIT_BLOCKS + WGT_BLOCKS)

__global__ __launch_bounds__(256)
void prep_kernel(const float* __restrict__ fc1w, const float* __restrict__ fc2w,
                 const float* __restrict__ ew1,  const float* __restrict__ ew2,
                 const float* __restrict__ tw1,  fp16* __restrict__ T,
                 const float* __restrict__ cls,  fp16* __restrict__ c0,
                 fp16* __restrict__ c1,
                 const float* __restrict__ tb2,  float* __restrict__ out,
                 const float* __restrict__ wg,   float* __restrict__ wgt)
{
    const int b = blockIdx.x;
    const int tid = threadIdx.x;

    if (b < TRN_BLOCKS) {
        __shared__ float tile[32][33];
        const int z   = b >> 10;
        const int rem = b & 1023;
        const int k0  = (rem >> 5) << 5;
        const int n0  = (rem & 31) << 5;
        const int tx  = tid & 31, ty = tid >> 5;
        const float* src;
        if      (z == 0)  src = fc1w;
        else if (z == 1)  src = fc2w;
        else if (z < 8)   src = ew1 + (long)(z - 2)  * HH_;
        else if (z < 14)  src = ew2 + (long)(z - 8)  * HH_;
        else              src = tw1 + (long)(z - 14) * HH_;
        const long ob = (long)z * 2 * HH_;
#pragma unroll
        for (int i = ty; i < 32; i += 8)
            tile[i][tx] = src[(long)(k0 + i) * HDIM + n0 + tx];
        __syncthreads();
#pragma unroll
        for (int i = ty; i < 32; i += 8) {
            const float v = tile[tx][i];
            const fp16 h = __float2half_rn(v);
            const long o = ob + (long)(n0 + i) * HDIM + k0 + tx;
            T[o] = h;
            T[o + HH_] = __float2half_rn(v - __half2float(h));
        }
    } else if (b < TRN_BLOCKS + CVT_BLOCKS) {
        const long base = ((long)(b - TRN_BLOCKS) * 256 + tid) * 4;
        const float4 v = *reinterpret_cast<const float4*>(cls + base);
        fp16 h0 = __float2half_rn(v.x), h1 = __float2half_rn(v.y);
        fp16 h2 = __float2half_rn(v.z), h3 = __float2half_rn(v.w);
        uint2 hp, lp;
        hp.x = (uint32_t)__half_as_ushort(h0) | ((uint32_t)__half_as_ushort(h1) << 16);
        hp.y = (uint32_t)__half_as_ushort(h2) | ((uint32_t)__half_as_ushort(h3) << 16);
        fp16 l0 = __float2half_rn(v.x - __half2float(h0));
        fp16 l1 = __float2half_rn(v.y - __half2float(h1));
        fp16 l2 = __float2half_rn(v.z - __half2float(h2));
        fp16 l3 = __float2half_rn(v.w - __half2float(h3));
        lp.x = (uint32_t)__half_as_ushort(l0) | ((uint32_t)__half_as_ushort(l1) << 16);
        lp.y = (uint32_t)__half_as_ushort(l2) | ((uint32_t)__half_as_ushort(l3) << 16);
        *reinterpret_cast<uint2*>(c0 + base) = hp;
        *reinterpret_cast<uint2*>(c1 + base) = lp;
    } else if (b < TRN_BLOCKS + CVT_BLOCKS + INIT_BLOCKS) {
        const int i = (b - TRN_BLOCKS - CVT_BLOCKS) * 256 + tid;
        if (i < NTASK * NROWS) out[i] = tb2[i / NROWS];
    } else {
        // wgate transpose: dst[t][e][h] = src[t][h][e]
        const int i = (b - TRN_BLOCKS - CVT_BLOCKS - INIT_BLOCKS) * 256 + tid;
        const int t = i / (NEXP * HDIM);
        const int r = i - t * (NEXP * HDIM);
        const int e = r / HDIM;
        const int h = r - e * HDIM;
        wgt[i] = wg[(long)t * HDIM * NEXP + (long)h * NEXP + e];
    }
}

// Gating: one warp per (t, n); coalesced float4 weight loads from wgate^T.
__global__ __launch_bounds__(256)
void gate_kernel(const fp16* __restrict__ h0, const fp16* __restrict__ h1,
                 const float* __restrict__ wgt, float* __restrict__ gates)
{
    const int warp = (blockIdx.x * blockDim.x + threadIdx.x) >> 5;
    const int lane = threadIdx.x & 31;
    if (warp >= NTASK * NROWS) return;
    const int t = warp / NROWS;
    const int n = warp - t * NROWS;

    float acc[NEXP];
#pragma unroll
    for (int e = 0; e < NEXP; e++) acc[e] = 0.f;

    const fp16* hr0 = h0 + (long)n * HDIM;
    const fp16* hr1 = h1 + (long)n * HDIM;
    const float* wt = wgt + (long)t * NEXP * HDIM;

#pragma unroll
    for (int it = 0; it < 8; it++) {
        const int base = it * 128 + lane * 4;
        const uint2 p0 = *reinterpret_cast<const uint2*>(hr0 + base);
        const uint2 p1 = *reinterpret_cast<const uint2*>(hr1 + base);
        float hv[4];
        {
            float2 a0 = __half22float2(*reinterpret_cast<const __half2*>(&p0.x));
            float2 a1 = __half22float2(*reinterpret_cast<const __half2*>(&p0.y));
            float2 b0 = __half22float2(*reinterpret_cast<const __half2*>(&p1.x));
            float2 b1 = __half22float2(*reinterpret_cast<const __half2*>(&p1.y));
            hv[0] = a0.x + b0.x; hv[1] = a0.y + b0.y;
            hv[2] = a1.x + b1.x; hv[3] = a1.y + b1.y;
        }
#pragma unroll
        for (int e = 0; e < NEXP; e++) {
            const float4 w = *reinterpret_cast<const float4*>(wt + e * HDIM + base);
            acc[e] = fmaf(hv[0], w.x, acc[e]);
            acc[e] = fmaf(hv[1], w.y, acc[e]);
            acc[e] = fmaf(hv[2], w.z, acc[e]);
            acc[e] = fmaf(hv[3], w.w, acc[e]);
        }
    }
#pragma unroll
    for (int off = 16; off > 0; off >>= 1)
#pragma unroll
        for (int e = 0; e < NEXP; e++)
            acc[e] += __shfl_xor_sync(0xffffffffu, acc[e], off);

    if (lane == 0) {
        float v[NEXP];
#pragma unroll
        for (int e = 0; e < NEXP; e++) v[e] = acc[e];
        int ti[TOPK]; float tv[TOPK];
#pragma unroll
        for (int s = 0; s < TOPK; s++) {
            int bi = 0; float bv = v[0];
#pragma unroll
            for (int e = 1; e < NEXP; e++) if (v[e] > bv) { bv = v[e]; bi = e; }
            ti[s] = bi; tv[s] = bv; v[bi] = -INFINITY;
        }
        const float m = tv[0];
        float w[TOPK], s = 0.f;
#pragma unroll
        for (int k = 0; k < TOPK; k++) { w[k] = expf(tv[k] - m); s += w[k]; }
        const float inv = 1.f / s;
        float gv[NEXP];
#pragma unroll
        for (int e = 0; e < NEXP; e++) gv[e] = 0.f;
#pragma unroll
        for (int k = 0; k < TOPK; k++) gv[ti[k]] = w[k] * inv;
        float* gp = gates + ((long)t * NROWS + n) * NEXP;
#pragma unroll
        for (int e = 0; e < NEXP; e++) gp[e] = gv[e];
    }
}

// Combine (R9-proven, vectorized x4)
__global__ __launch_bounds__(256)
void combine_kernel(const float* __restrict__ eo, const float* __restrict__ gates,
                    fp16* __restrict__ m0, fp16* __restrict__ m1)
{
    const long q = (long)blockIdx.x * blockDim.x + threadIdx.x;
    const long base = q * 4;
    if (base >= NH_) return;
    const int n = (int)(base >> 10);

    float4 v[NEXP];
#pragma unroll
    for (int e = 0; e < NEXP; e++)
        v[e] = *reinterpret_cast<const float4*>(eo + (long)e * NH_ + base);

#pragma unroll
    for (int t = 0; t < NTASK; t++) {
        const float* gp = gates + ((long)t * NROWS + n) * NEXP;
        float g[NEXP];
#pragma unroll
        for (int e = 0; e < NEXP; e++) g[e] = gp[e];
        float r[4] = {0.f, 0.f, 0.f, 0.f};
#pragma unroll
        for (int e = 0; e < NEXP; e++) {
            r[0] = fmaf(g[e], v[e].x, r[0]);
            r[1] = fmaf(g[e], v[e].y, r[1]);
            r[2] = fmaf(g[e], v[e].z, r[2]);
            r[3] = fmaf(g[e], v[e].w, r[3]);
        }
        uint2 hp, lp;
        {
            fp16 h0 = __float2half_rn(r[0]), h1 = __float2half_rn(r[1]);
            fp16 h2 = __float2half_rn(r[2]), h3 = __float2half_rn(r[3]);
            hp.x = (uint32_t)__half_as_ushort(h0) | ((uint32_t)__half_as_ushort(h1) << 16);
            hp.y = (uint32_t)__half_as_ushort(h2) | ((uint32_t)__half_as_ushort(h3) << 16);
            fp16 l0 = __float2half_rn(r[0] - __half2float(h0));
            fp16 l1 = __float2half_rn(r[1] - __half2float(h1));
            fp16 l2 = __float2half_rn(r[2] - __half2float(h2));
            fp16 l3 = __float2half_rn(r[3] - __half2float(h3));
            lp.x = (uint32_t)__half_as_ushort(l0) | ((uint32_t)__half_as_ushort(l1) << 16);
            lp.y = (uint32_t)__half_as_ushort(l2) | ((uint32_t)__half_as_ushort(l3) << 16);
        }
        *reinterpret_cast<uint2*>(m0 + (long)t * NH_ + base) = hp;
        *reinterpret_cast<uint2*>(m1 + (long)t * NH_ + base) = lp;
    }
}

// ================================ launch ===================================
extern "C" void kernel_launch(void* const* d_in, const int* in_sizes, int n_in,
                              void* d_out, int out_size)
{
    const float* cls   = (const float*)d_in[0];
    const float* fc1w  = (const float*)d_in[1];
    const float* fc1b  = (const float*)d_in[2];
    const float* fc2w  = (const float*)d_in[3];
    const float* fc2b  = (const float*)d_in[4];
    const float* wgate = (const float*)d_in[5];
    const float* ew1   = (const float*)d_in[6];
    const float* eb1   = (const float*)d_in[7];
    const float* ew2   = (const float*)d_in[8];
    const float* eb2   = (const float*)d_in[9];
    const float* tw1   = (const float*)d_in[10];
    const float* tb1   = (const float*)d_in[11];
    const float* tw2   = (const float*)d_in[12];
    const float* tb2   = (const float*)d_in[13];
    float* out = (float*)d_out;

    fp16 *clsS, *h1S, *hS, *ehS, *moS, *wt;
    float *eo, *gates, *wgt;
    cudaGetSymbolAddress((void**)&clsS, g_cls);
    cudaGetSymbolAddress((void**)&h1S,  g_h1);
    cudaGetSymbolAddress((void**)&hS,   g_h);
    cudaGetSymbolAddress((void**)&ehS,  g_eh);
    cudaGetSymbolAddress((void**)&eo,   g_eo);
    cudaGetSymbolAddress((void**)&moS,  g_mo);
    cudaGetSymbolAddress((void**)&gates,g_gates);
    cudaGetSymbolAddress((void**)&wt,   g_wt);
    cudaGetSymbolAddress((void**)&wgt,  g_wgt);

    fp16* fc1t = wt;                 // unit 0
    fp16* fc2t = wt + 2 * HH_;       // unit 1
    fp16* ew1t = wt + 4 * HH_;       // units 2..7
    fp16* ew2t = wt + 16 * HH_;      // units 8..13
    fp16* tw1t = wt + 28 * HH_;      // units 14..16

    cudaFuncSetAttribute((const void*)mma_gemm<true,  true,  false>,
                         cudaFuncAttributeMaxDynamicSharedMemorySize, SM_BYTES);
    cudaFuncSetAttribute((const void*)mma_gemm<false, true,  false>,
                         cudaFuncAttributeMaxDynamicSharedMemorySize, SM_BYTES);
    cudaFuncSetAttribute((const void*)mma_gemm<false, false, false>,
                         cudaFuncAttributeMaxDynamicSharedMemorySize, SM_BYTES);
    cudaFuncSetAttribute((const void*)mma_gemm<false, false, true>,
                         cudaFuncAttributeMaxDynamicSharedMemorySize, SM_BYTES);

    const dim3 blk(256);
    const dim3 gblk(GEMM_THREADS);
    const dim3 g1(HDIM / BN, NROWS / BM, 1);
    const dim3 gE(HDIM / BN, NROWS / BM, NEXP);
    const dim3 gT(HDIM / BN, NROWS / BM, NTASK);

    // 0: fused prep — weight transposes + input split + out init + wgate^T
    prep_kernel<<<PREP_BLOCKS, blk>>>(fc1w, fc2w, ew1, ew2, tw1, wt,
                                      cls, clsS, clsS + NH_, tb2, out,
                                      wgate, wgt);

    // 1: fc1 (relu, split out)
    mma_gemm<true, true, false><<<g1, gblk, SM_BYTES>>>(
        clsS, clsS + NH_, fc1t, fc1t + HH_, fc1b,
        nullptr, h1S, h1S + NH_, nullptr, nullptr,
        0, 0, 0, 0, 0);
    // 2: fc2 (split out; gate reads comps)
    mma_gemm<false, true, false><<<g1, gblk, SM_BYTES>>>(
        h1S, h1S + NH_, fc2t, fc2t + HH_, fc2b,
        nullptr, hS, hS + NH_, nullptr, nullptr,
        0, 0, 0, 0, 0);

    // 3: gating (coalesced wgate^T)
    gate_kernel<<<(NTASK * NROWS) / 8, blk>>>(hS, hS + NH_, wgt, gates);

    // 4: experts layer 1 (relu, split out)
    mma_gemm<true, true, false><<<gE, gblk, SM_BYTES>>>(
        hS, hS + NH_, ew1t, ew1t + HH_, eb1,
        nullptr, ehS, ehS + (long)NEXP * NH_, nullptr, nullptr,
        0, 2 * HH_, HDIM, NH_, 0);
    // 5: experts layer 2 (fp32 out)
    mma_gemm<false, false, false><<<gE, gblk, SM_BYTES>>>(
        ehS, ehS + (long)NEXP * NH_, ew2t, ew2t + HH_, eb2,
        eo, nullptr, nullptr, nullptr, nullptr,
        NH_, 2 * HH_, HDIM, NH_, 0);

    // 6: gate combine (vectorized x4)
    combine_kernel<<<(unsigned)(NH_ / 4 / 256), blk>>>(eo, gates, moS,
                                                       moS + (long)NTASK * NH_);

    // 7: towers (fused relu + tw2 reduction; out pre-initialized by prep)
    mma_gemm<false, false, true><<<gT, gblk, SM_BYTES>>>(
        moS, moS + (long)NTASK * NH_, tw1t, tw1t + HH_, tb1,
        nullptr, nullptr, nullptr, tw2, out,
        NH_, 2 * HH_, HDIM, 0, HDIM);
}

// round 14
// speedup vs baseline: 1.0831x; 1.0027x over previous
#include <cuda_runtime.h>
#include <cuda_fp16.h>
#include <math.h>
#include <stdint.h>

#define NROWS 16384
#define HDIM  1024
#define NEXP  6
#define NTASK 3
#define TOPK  3

typedef __half fp16;
#define NH_ ((long)NROWS * HDIM)          // 16777216
#define HH_ ((long)HDIM * HDIM)           // 1048576

// =============================== Scratch ===================================
__device__ __align__(256) fp16  g_cls[2 * NH_];
__device__ __align__(256) fp16  g_h1 [2 * NH_];
__device__ __align__(256) fp16  g_h  [2 * NH_];
__device__ __align__(256) fp16  g_eh [2 * NEXP * NH_];
__device__ __align__(256) float g_eo [NEXP * NH_];
__device__ __align__(256) fp16  g_mo [2 * NTASK * NH_];
__device__ __align__(256) float g_gates[(long)NTASK * NROWS * NEXP];
__device__ __align__(256) fp16  g_wt [34 * HH_];
__device__ __align__(256) float g_wgt[NTASK * NEXP * HDIM];   // wgate^T [t][e][h]

// =============================== PTX helpers ===============================
__device__ __forceinline__ uint32_t smem_u32(const void* p) {
    uint32_t a;
    asm("{ .reg .u64 t; cvta.to.shared.u64 t, %1; cvt.u32.u64 %0, t; }" : "=r"(a) : "l"(p));
    return a;
}
__device__ __forceinline__ void cp16(uint32_t s, const void* g) {
    asm volatile("cp.async.cg.shared.global [%0], [%1], 16;" :: "r"(s), "l"(g) : "memory");
}
#define CP_COMMIT() asm volatile("cp.async.commit_group;" ::: "memory")
#define CP_WAIT1()  asm volatile("cp.async.wait_group 1;" ::: "memory")
#define CP_WAIT0()  asm volatile("cp.async.wait_group 0;" ::: "memory")

__device__ __forceinline__ void ldsm4(uint32_t (&r)[4], uint32_t addr) {
    asm volatile("ldmatrix.sync.aligned.m8n8.x4.shared.b16 {%0,%1,%2,%3}, [%4];"
                 : "=r"(r[0]), "=r"(r[1]), "=r"(r[2]), "=r"(r[3]) : "r"(addr));
}
__device__ __forceinline__ void mma_fp16(float (&d)[4], const uint32_t (&a)[4],
                                         uint32_t b0, uint32_t b1) {
    asm volatile(
        "mma.sync.aligned.m16n8k16.row.col.f32.f16.f16.f32 "
        "{%0,%1,%2,%3}, {%4,%5,%6,%7}, {%8,%9}, {%0,%1,%2,%3};"
        : "+f"(d[0]), "+f"(d[1]), "+f"(d[2]), "+f"(d[3])
        : "r"(a[0]), "r"(a[1]), "r"(a[2]), "r"(a[3]), "r"(b0), "r"(b1));
}

// ============================ split-fp16 GEMM ==============================
// FROZEN R8/R11 loop: batched ldsm, term-major mma, ldstage AFTER compute.
#define BM 128
#define BN 128
#define BK 32
#define NKCH (HDIM / BK)          // 32
#define MB_  8192                 // one 128x32 fp16 matrix, 64B rows
#define STG  (4 * MB_)            // 32768 per stage
#define SM_BYTES (3 * STG)        // 98304
#define GEMM_THREADS 128

__device__ __forceinline__ uint32_t swz(int row, int c16) {
    return (uint32_t)(row * 64 + ((c16 ^ ((row >> 1) & 3)) << 4));
}

template <bool RELU, bool WSPL, bool TOWER>
__global__ void __launch_bounds__(GEMM_THREADS, 2)
mma_gemm(const fp16* __restrict__ A0, const fp16* __restrict__ A1,
         const fp16* __restrict__ B0, const fp16* __restrict__ B1,
         const float* __restrict__ bias,
         float* __restrict__ Cf, fp16* __restrict__ C0, fp16* __restrict__ C1,
         const float* __restrict__ w2, float* __restrict__ outT,
         long sA, long sB, long sBias, long sC, long sW2)
{
    extern __shared__ char smem[];
    const uint32_t smbase = smem_u32(smem);
    const int tid = threadIdx.x, wid = tid >> 5, lane = tid & 31;
    const int z = blockIdx.z;
    const long row0 = (long)blockIdx.y * BM;
    const int  n0   = blockIdx.x * BN;

    const fp16* Ag0 = A0 + z * sA + row0 * HDIM;
    const fp16* Ag1 = A1 + z * sA + row0 * HDIM;
    const fp16* Bg0 = B0 + z * sB + (long)n0 * HDIM;
    const fp16* Bg1 = B1 + z * sB + (long)n0 * HDIM;

    const int ldr0 = tid >> 2, ldch = tid & 3;
    auto ldstage = [&](int buf, int kc0) {
        const uint32_t sb = smbase + buf * STG;
#pragma unroll
        for (int i = 0; i < 4; i++) {
            const int r = ldr0 + 32 * i;
            const long g = (long)r * HDIM + kc0 + ldch * 8;
            const uint32_t so = swz(r, ldch);
            cp16(sb + 0 * MB_ + so, Ag0 + g);
            cp16(sb + 1 * MB_ + so, Ag1 + g);
            cp16(sb + 2 * MB_ + so, Bg0 + g);
            cp16(sb + 3 * MB_ + so, Bg1 + g);
        }
    };

    float acc[4][8][4];
#pragma unroll
    for (int mt = 0; mt < 4; mt++)
#pragma unroll
        for (int nt = 0; nt < 8; nt++)
#pragma unroll
            for (int q = 0; q < 4; q++) acc[mt][nt][q] = 0.f;

    const int wm = (wid & 1) * 64;
    const int wn = (wid >> 1) * 64;
    const int grp = lane >> 3, lr = lane & 7;
    const int arow = lr + ((grp & 1) << 3);
    const int ac16 = grp >> 1;
    const int brow = lr + ((grp >> 1) << 3);
    const int bc16 = grp & 1;

    uint32_t abase[4], axm[4], bbase[4], bxm[4];
#pragma unroll
    for (int mt = 0; mt < 4; mt++) {
        const int r = wm + mt * 16 + arow;
        abase[mt] = (uint32_t)(r * 64);
        axm[mt]   = (uint32_t)((r >> 1) & 3);
    }
#pragma unroll
    for (int np = 0; np < 4; np++) {
        const int r = wn + np * 16 + brow;
        bbase[np] = (uint32_t)(r * 64);
        bxm[np]   = (uint32_t)((r >> 1) & 3);
    }

    ldstage(0, 0);           CP_COMMIT();
    ldstage(1, BK);          CP_COMMIT();

    for (int c = 0; c < NKCH; c++) {
        if (c + 1 < NKCH) CP_WAIT1(); else CP_WAIT0();
        __syncthreads();     // chunk c published; buffer (c+2)%3 free

        const uint32_t sb = smbase + (c % 3) * STG;
#pragma unroll
        for (int ks = 0; ks < 2; ks++) {
            uint32_t af[2][4][4];
            uint32_t bfr[2][4][4];
            const uint32_t ka = (uint32_t)(ks * 2 + ac16);
            const uint32_t kb = (uint32_t)(ks * 2 + bc16);
#pragma unroll
            for (int sc = 0; sc < 2; sc++)
#pragma unroll
                for (int mt = 0; mt < 4; mt++)
                    ldsm4(af[sc][mt],
                          sb + sc * MB_ + abase[mt] + ((ka ^ axm[mt]) << 4));
#pragma unroll
            for (int sc = 0; sc < 2; sc++)
#pragma unroll
                for (int np = 0; np < 4; np++)
                    ldsm4(bfr[sc][np],
                          sb + (2 + sc) * MB_ + bbase[np] + ((kb ^ bxm[np]) << 4));

#pragma unroll
            for (int term = 0; term < 3; term++) {
                const int ai = (term == 2) ? 1 : 0;
                const int bi = (term == 1) ? 1 : 0;
#pragma unroll
                for (int np = 0; np < 4; np++)
#pragma unroll
                    for (int mt = 0; mt < 4; mt++) {
                        mma_fp16(acc[mt][2 * np],     af[ai][mt],
                                 bfr[bi][np][0], bfr[bi][np][1]);
                        mma_fp16(acc[mt][2 * np + 1], af[ai][mt],
                                 bfr[bi][np][2], bfr[bi][np][3]);
                    }
            }
        }

        if (c + 2 < NKCH) { ldstage((c + 2) % 3, (c + 2) * BK); CP_COMMIT(); }
    }

    // ------------------------------ epilogue ------------------------------
    const float* biasz = bias + z * sBias;
    const float* w2z   = TOWER ? (w2 + z * sW2) : nullptr;

#pragma unroll
    for (int mt = 0; mt < 4; mt++) {
#pragma unroll
        for (int half = 0; half < 2; half++) {
            const long gr = row0 + wm + mt * 16 + (lane >> 2) + half * 8;
            float p = 0.f;
#pragma unroll
            for (int nt = 0; nt < 8; nt++) {
                const int cc = n0 + wn + nt * 8 + (lane & 3) * 2;
                float v0 = acc[mt][nt][half * 2 + 0] + biasz[cc];
                float v1 = acc[mt][nt][half * 2 + 1] + biasz[cc + 1];
                if (RELU || TOWER) { v0 = fmaxf(v0, 0.f); v1 = fmaxf(v1, 0.f); }
                if (TOWER) {
                    p = fmaf(v0, w2z[cc], p);
                    p = fmaf(v1, w2z[cc + 1], p);
                } else {
                    const long off = z * sC + gr * HDIM + cc;
                    if (Cf != nullptr)
                        *reinterpret_cast<float2*>(&Cf[off]) = make_float2(v0, v1);
                    if (WSPL) {
                        fp16 h0 = __float2half_rn(v0), h1 = __float2half_rn(v1);
                        fp16 l0 = __float2half_rn(v0 - __half2float(h0));
                        fp16 l1 = __float2half_rn(v1 - __half2float(h1));
                        *reinterpret_cast<uint32_t*>(&C0[off]) =
                            (uint32_t)__half_as_ushort(h0) |
                            ((uint32_t)__half_as_ushort(h1) << 16);
                        *reinterpret_cast<uint32_t*>(&C1[off]) =
                            (uint32_t)__half_as_ushort(l0) |
                            ((uint32_t)__half_as_ushort(l1) << 16);
                    }
                }
            }
            if (TOWER) {
                p += __shfl_down_sync(0xffffffffu, p, 2);
                p += __shfl_down_sync(0xffffffffu, p, 1);
                if ((lane & 3) == 0)
                    atomicAdd(&outT[(long)z * NROWS + gr], p);
            }
        }
    }
}

// ===================== fused prep kernel (one launch) ======================
#define TRN_BLOCKS  (17 * 1024)
#define CVT_BLOCKS  ((int)(NH_ / 4 / 256))          // 16384
#define INIT_BLOCKS ((NTASK * NROWS) / 256)         // 192
#define WGT_BLOCKS  ((NTASK * NEXP * HDIM) / 256)   // 72
#define PREP_BLOCKS (TRN_BLOCKS + CVT_BLOCKS + INIT_BLOCKS + WGT_BLOCKS)

__global__ __launch_bounds__(256)
void prep_kernel(const float* __restrict__ fc1w, const float* __restrict__ fc2w,
                 const float* __restrict__ ew1,  const float* __restrict__ ew2,
                 const float* __restrict__ tw1,  fp16* __restrict__ T,
                 const float* __restrict__ cls,  fp16* __restrict__ c0,
                 fp16* __restrict__ c1,
                 const float* __restrict__ tb2,  float* __restrict__ out,
                 const float* __restrict__ wg,   float* __restrict__ wgt)
{
    const int b = blockIdx.x;
    const int tid = threadIdx.x;

    if (b < TRN_BLOCKS) {
        __shared__ float tile[32][33];
        const int z   = b >> 10;
        const int rem = b & 1023;
        const int k0  = (rem >> 5) << 5;
        const int n0  = (rem & 31) << 5;
        const int tx  = tid & 31, ty = tid >> 5;
        const float* src;
        if      (z == 0)  src = fc1w;
        else if (z == 1)  src = fc2w;
        else if (z < 8)   src = ew1 + (long)(z - 2)  * HH_;
        else if (z < 14)  src = ew2 + (long)(z - 8)  * HH_;
        else              src = tw1 + (long)(z - 14) * HH_;
        const long ob = (long)z * 2 * HH_;
#pragma unroll
        for (int i = ty; i < 32; i += 8)
            tile[i][tx] = src[(long)(k0 + i) * HDIM + n0 + tx];
        __syncthreads();
#pragma unroll
        for (int i = ty; i < 32; i += 8) {
            const float v = tile[tx][i];
            const fp16 h = __float2half_rn(v);
            const long o = ob + (long)(n0 + i) * HDIM + k0 + tx;
            T[o] = h;
            T[o + HH_] = __float2half_rn(v - __half2float(h));
        }
    } else if (b < TRN_BLOCKS + CVT_BLOCKS) {
        const long base = ((long)(b - TRN_BLOCKS) * 256 + tid) * 4;
        const float4 v = *reinterpret_cast<const float4*>(cls + base);
        fp16 h0 = __float2half_rn(v.x), h1 = __float2half_rn(v.y);
        fp16 h2 = __float2half_rn(v.z), h3 = __float2half_rn(v.w);
        uint2 hp, lp;
        hp.x = (uint32_t)__half_as_ushort(h0) | ((uint32_t)__half_as_ushort(h1) << 16);
        hp.y = (uint32_t)__half_as_ushort(h2) | ((uint32_t)__half_as_ushort(h3) << 16);
        fp16 l0 = __float2half_rn(v.x - __half2float(h0));
        fp16 l1 = __float2half_rn(v.y - __half2float(h1));
        fp16 l2 = __float2half_rn(v.z - __half2float(h2));
        fp16 l3 = __float2half_rn(v.w - __half2float(h3));
        lp.x = (uint32_t)__half_as_ushort(l0) | ((uint32_t)__half_as_ushort(l1) << 16);
        lp.y = (uint32_t)__half_as_ushort(l2) | ((uint32_t)__half_as_ushort(l3) << 16);
        *reinterpret_cast<uint2*>(c0 + base) = hp;
        *reinterpret_cast<uint2*>(c1 + base) = lp;
    } else if (b < TRN_BLOCKS + CVT_BLOCKS + INIT_BLOCKS) {
        const int i = (b - TRN_BLOCKS - CVT_BLOCKS) * 256 + tid;
        if (i < NTASK * NROWS) out[i] = tb2[i / NROWS];
    } else {
        const int i = (b - TRN_BLOCKS - CVT_BLOCKS - INIT_BLOCKS) * 256 + tid;
        const int t = i / (NEXP * HDIM);
        const int r = i - t * (NEXP * HDIM);
        const int e = r / HDIM;
        const int h = r - e * HDIM;
        wgt[i] = wg[(long)t * HDIM * NEXP + (long)h * NEXP + e];
    }
}

// Gating: one warp per (t, n); block-shared wgate^T tile (all 8 warps in a
// block share the same task t since NROWS % 8 == 0).
__global__ __launch_bounds__(256)
void gate_kernel(const fp16* __restrict__ h0, const fp16* __restrict__ h1,
                 const float* __restrict__ wgt, float* __restrict__ gates)
{
    __shared__ float ws[NEXP * HDIM];        // 24 KB
    const int tid  = threadIdx.x;
    const int lane = tid & 31;
    const int warp = blockIdx.x * 8 + (tid >> 5);
    const int t = warp / NROWS;
    const int n = warp - t * NROWS;

    // cooperative load of wgt[t] into smem (1536 float4 / 256 threads = 6)
    {
        const float4* src = reinterpret_cast<const float4*>(wgt + (long)t * NEXP * HDIM);
        float4* dst = reinterpret_cast<float4*>(ws);
#pragma unroll
        for (int i = 0; i < 6; i++)
            dst[tid + 256 * i] = src[tid + 256 * i];
    }
    __syncthreads();

    float acc[NEXP];
#pragma unroll
    for (int e = 0; e < NEXP; e++) acc[e] = 0.f;

    const fp16* hr0 = h0 + (long)n * HDIM;
    const fp16* hr1 = h1 + (long)n * HDIM;

#pragma unroll
    for (int it = 0; it < 8; it++) {
        const int base = it * 128 + lane * 4;
        const uint2 p0 = *reinterpret_cast<const uint2*>(hr0 + base);
        const uint2 p1 = *reinterpret_cast<const uint2*>(hr1 + base);
        float hv[4];
        {
            float2 a0 = __half22float2(*reinterpret_cast<const __half2*>(&p0.x));
            float2 a1 = __half22float2(*reinterpret_cast<const __half2*>(&p0.y));
            float2 b0 = __half22float2(*reinterpret_cast<const __half2*>(&p1.x));
            float2 b1 = __half22float2(*reinterpret_cast<const __half2*>(&p1.y));
            hv[0] = a0.x + b0.x; hv[1] = a0.y + b0.y;
            hv[2] = a1.x + b1.x; hv[3] = a1.y + b1.y;
        }
#pragma unroll
        for (int e = 0; e < NEXP; e++) {
            const float4 w = *reinterpret_cast<const float4*>(&ws[e * HDIM + base]);
            acc[e] = fmaf(hv[0], w.x, acc[e]);
            acc[e] = fmaf(hv[1], w.y, acc[e]);
            acc[e] = fmaf(hv[2], w.z, acc[e]);
            acc[e] = fmaf(hv[3], w.w, acc[e]);
        }
    }
#pragma unroll
    for (int off = 16; off > 0; off >>= 1)
#pragma unroll
        for (int e = 0; e < NEXP; e++)
            acc[e] += __shfl_xor_sync(0xffffffffu, acc[e], off);

    if (lane == 0) {
        float v[NEXP];
#pragma unroll
        for (int e = 0; e < NEXP; e++) v[e] = acc[e];
        int ti[TOPK]; float tv[TOPK];
#pragma unroll
        for (int s = 0; s < TOPK; s++) {
            int bi = 0; float bv = v[0];
#pragma unroll
            for (int e = 1; e < NEXP; e++) if (v[e] > bv) { bv = v[e]; bi = e; }
            ti[s] = bi; tv[s] = bv; v[bi] = -INFINITY;
        }
        const float m = tv[0];
        float w[TOPK], s = 0.f;
#pragma unroll
        for (int k = 0; k < TOPK; k++) { w[k] = expf(tv[k] - m); s += w[k]; }
        const float inv = 1.f / s;
        float gv[NEXP];
#pragma unroll
        for (int e = 0; e < NEXP; e++) gv[e] = 0.f;
#pragma unroll
        for (int k = 0; k < TOPK; k++) gv[ti[k]] = w[k] * inv;
        float* gp = gates + ((long)t * NROWS + n) * NEXP;
#pragma unroll
        for (int e = 0; e < NEXP; e++) gp[e] = gv[e];
    }
}

// Combine (R9-proven, vectorized x4)
__global__ __launch_bounds__(256)
void combine_kernel(const float* __restrict__ eo, const float* __restrict__ gates,
                    fp16* __restrict__ m0, fp16* __restrict__ m1)
{
    const long q = (long)blockIdx.x * blockDim.x + threadIdx.x;
    const long base = q * 4;
    if (base >= NH_) return;
    const int n = (int)(base >> 10);

    float4 v[NEXP];
#pragma unroll
    for (int e = 0; e < NEXP; e++)
        v[e] = *reinterpret_cast<const float4*>(eo + (long)e * NH_ + base);

#pragma unroll
    for (int t = 0; t < NTASK; t++) {
        const float* gp = gates + ((long)t * NROWS + n) * NEXP;
        float g[NEXP];
#pragma unroll
        for (int e = 0; e < NEXP; e++) g[e] = gp[e];
        float r[4] = {0.f, 0.f, 0.f, 0.f};
#pragma unroll
        for (int e = 0; e < NEXP; e++) {
            r[0] = fmaf(g[e], v[e].x, r[0]);
            r[1] = fmaf(g[e], v[e].y, r[1]);
            r[2] = fmaf(g[e], v[e].z, r[2]);
            r[3] = fmaf(g[e], v[e].w, r[3]);
        }
        uint2 hp, lp;
        {
            fp16 h0 = __float2half_rn(r[0]), h1 = __float2half_rn(r[1]);
            fp16 h2 = __float2half_rn(r[2]), h3 = __float2half_rn(r[3]);
            hp.x = (uint32_t)__half_as_ushort(h0) | ((uint32_t)__half_as_ushort(h1) << 16);
            hp.y = (uint32_t)__half_as_ushort(h2) | ((uint32_t)__half_as_ushort(h3) << 16);
            fp16 l0 = __float2half_rn(r[0] - __half2float(h0));
            fp16 l1 = __float2half_rn(r[1] - __half2float(h1));
            fp16 l2 = __float2half_rn(r[2] - __half2float(h2));
            fp16 l3 = __float2half_rn(r[3] - __half2float(h3));
            lp.x = (uint32_t)__half_as_ushort(l0) | ((uint32_t)__half_as_ushort(l1) << 16);
            lp.y = (uint32_t)__half_as_ushort(l2) | ((uint32_t)__half_as_ushort(l3) << 16);
        }
        *reinterpret_cast<uint2*>(m0 + (long)t * NH_ + base) = hp;
        *reinterpret_cast<uint2*>(m1 + (long)t * NH_ + base) = lp;
    }
}

// ================================ launch ===================================
extern "C" void kernel_launch(void* const* d_in, const int* in_sizes, int n_in,
                              void* d_out, int out_size)
{
    const float* cls   = (const float*)d_in[0];
    const float* fc1w  = (const float*)d_in[1];
    const float* fc1b  = (const float*)d_in[2];
    const float* fc2w  = (const float*)d_in[3];
    const float* fc2b  = (const float*)d_in[4];
    const float* wgate = (const float*)d_in[5];
    const float* ew1   = (const float*)d_in[6];
    const float* eb1   = (const float*)d_in[7];
    const float* ew2   = (const float*)d_in[8];
    const float* eb2   = (const float*)d_in[9];
    const float* tw1   = (const float*)d_in[10];
    const float* tb1   = (const float*)d_in[11];
    const float* tw2   = (const float*)d_in[12];
    const float* tb2   = (const float*)d_in[13];
    float* out = (float*)d_out;

    fp16 *clsS, *h1S, *hS, *ehS, *moS, *wt;
    float *eo, *gates, *wgt;
    cudaGetSymbolAddress((void**)&clsS, g_cls);
    cudaGetSymbolAddress((void**)&h1S,  g_h1);
    cudaGetSymbolAddress((void**)&hS,   g_h);
    cudaGetSymbolAddress((void**)&ehS,  g_eh);
    cudaGetSymbolAddress((void**)&eo,   g_eo);
    cudaGetSymbolAddress((void**)&moS,  g_mo);
    cudaGetSymbolAddress((void**)&gates,g_gates);
    cudaGetSymbolAddress((void**)&wt,   g_wt);
    cudaGetSymbolAddress((void**)&wgt,  g_wgt);

    fp16* fc1t = wt;                 // unit 0
    fp16* fc2t = wt + 2 * HH_;       // unit 1
    fp16* ew1t = wt + 4 * HH_;       // units 2..7
    fp16* ew2t = wt + 16 * HH_;      // units 8..13
    fp16* tw1t = wt + 28 * HH_;      // units 14..16

    cudaFuncSetAttribute((const void*)mma_gemm<true,  true,  false>,
                         cudaFuncAttributeMaxDynamicSharedMemorySize, SM_BYTES);
    cudaFuncSetAttribute((const void*)mma_gemm<false, true,  false>,
                         cudaFuncAttributeMaxDynamicSharedMemorySize, SM_BYTES);
    cudaFuncSetAttribute((const void*)mma_gemm<false, false, false>,
                         cudaFuncAttributeMaxDynamicSharedMemorySize, SM_BYTES);
    cudaFuncSetAttribute((const void*)mma_gemm<false, false, true>,
                         cudaFuncAttributeMaxDynamicSharedMemorySize, SM_BYTES);

    const dim3 blk(256);
    const dim3 gblk(GEMM_THREADS);
    const dim3 g1(HDIM / BN, NROWS / BM, 1);
    const dim3 gE(HDIM / BN, NROWS / BM, NEXP);
    const dim3 gT(HDIM / BN, NROWS / BM, NTASK);

    // 0: fused prep — weight transposes + input split + out init + wgate^T
    prep_kernel<<<PREP_BLOCKS, blk>>>(fc1w, fc2w, ew1, ew2, tw1, wt,
                                      cls, clsS, clsS + NH_, tb2, out,
                                      wgate, wgt);

    // 1: fc1 (relu, split out)
    mma_gemm<true, true, false><<<g1, gblk, SM_BYTES>>>(
        clsS, clsS + NH_, fc1t, fc1t + HH_, fc1b,
        nullptr, h1S, h1S + NH_, nullptr, nullptr,
        0, 0, 0, 0, 0);
    // 2: fc2 (split out; gate reads comps)
    mma_gemm<false, true, false><<<g1, gblk, SM_BYTES>>>(
        h1S, h1S + NH_, fc2t, fc2t + HH_, fc2b,
        nullptr, hS, hS + NH_, nullptr, nullptr,
        0, 0, 0, 0, 0);

    // 3: gating (smem-cached wgate^T)
    gate_kernel<<<(NTASK * NROWS) / 8, blk>>>(hS, hS + NH_, wgt, gates);

    // 4: experts layer 1 (relu, split out)
    mma_gemm<true, true, false><<<gE, gblk, SM_BYTES>>>(
        hS, hS + NH_, ew1t, ew1t + HH_, eb1,
        nullptr, ehS, ehS + (long)NEXP * NH_, nullptr, nullptr,
        0, 2 * HH_, HDIM, NH_, 0);
    // 5: experts layer 2 (fp32 out)
    mma_gemm<false, false, false><<<gE, gblk, SM_BYTES>>>(
        ehS, ehS + (long)NEXP * NH_, ew2t, ew2t + HH_, eb2,
        eo, nullptr, nullptr, nullptr, nullptr,
        NH_, 2 * HH_, HDIM, NH_, 0);

    // 6: gate combine (vectorized x4)
    combine_kernel<<<(unsigned)(NH_ / 4 / 256), blk>>>(eo, gates, moS,
                                                       moS + (long)NTASK * NH_);

    // 7: towers (fused relu + tw2 reduction; out pre-initialized by prep)
    mma_gemm<false, false, true><<<gT, gblk, SM_BYTES>>>(
        moS, moS + (long)NTASK * NH_, tw1t, tw1t + HH_, tb1,
        nullptr, nullptr, nullptr, tw2, out,
        NH_, 2 * HH_, HDIM, 0, HDIM);
}

// round 15
// speedup vs baseline: 1.0837x; 1.0005x over previous
#include <cuda_runtime.h>
#include <cuda_fp16.h>
#include <math.h>
#include <stdint.h>

#define NROWS 16384
#define HDIM  1024
#define NEXP  6
#define NTASK 3
#define TOPK  3

typedef __half fp16;
#define NH_ ((long)NROWS * HDIM)          // 16777216
#define HH_ ((long)HDIM * HDIM)           // 1048576

// =============================== Scratch ===================================
__device__ __align__(256) fp16  g_cls[2 * NH_];
__device__ __align__(256) fp16  g_h1 [2 * NH_];
__device__ __align__(256) fp16  g_h  [2 * NH_];
__device__ __align__(256) fp16  g_eh [2 * NEXP * NH_];
__device__ __align__(256) float g_eo [NEXP * NH_];
__device__ __align__(256) fp16  g_mo [2 * NTASK * NH_];
__device__ __align__(256) float g_gates[(long)NTASK * NROWS * NEXP];
__device__ __align__(256) fp16  g_wt [34 * HH_];
__device__ __align__(256) float g_wgt[NTASK * NEXP * HDIM];   // wgate^T [t][e][h]

// =============================== PTX helpers ===============================
__device__ __forceinline__ uint32_t smem_u32(const void* p) {
    uint32_t a;
    asm("{ .reg .u64 t; cvta.to.shared.u64 t, %1; cvt.u32.u64 %0, t; }" : "=r"(a) : "l"(p));
    return a;
}
__device__ __forceinline__ void cp16(uint32_t s, const void* g) {
    asm volatile("cp.async.cg.shared.global [%0], [%1], 16;" :: "r"(s), "l"(g) : "memory");
}
#define CP_COMMIT() asm volatile("cp.async.commit_group;" ::: "memory")
#define CP_WAIT1()  asm volatile("cp.async.wait_group 1;" ::: "memory")
#define CP_WAIT0()  asm volatile("cp.async.wait_group 0;" ::: "memory")

__device__ __forceinline__ void ldsm4(uint32_t (&r)[4], uint32_t addr) {
    asm volatile("ldmatrix.sync.aligned.m8n8.x4.shared.b16 {%0,%1,%2,%3}, [%4];"
                 : "=r"(r[0]), "=r"(r[1]), "=r"(r[2]), "=r"(r[3]) : "r"(addr));
}
__device__ __forceinline__ void mma_fp16(float (&d)[4], const uint32_t (&a)[4],
                                         uint32_t b0, uint32_t b1) {
    asm volatile(
        "mma.sync.aligned.m16n8k16.row.col.f32.f16.f16.f32 "
        "{%0,%1,%2,%3}, {%4,%5,%6,%7}, {%8,%9}, {%0,%1,%2,%3};"
        : "+f"(d[0]), "+f"(d[1]), "+f"(d[2]), "+f"(d[3])
        : "r"(a[0]), "r"(a[1]), "r"(a[2]), "r"(a[3]), "r"(b0), "r"(b1));
}

// ============================ split-fp16 GEMM ==============================
// FROZEN R8/R11 loop: batched ldsm, term-major mma, ldstage AFTER compute.
#define BM 128
#define BN 128
#define BK 32
#define NKCH (HDIM / BK)          // 32
#define MB_  8192                 // one 128x32 fp16 matrix, 64B rows
#define STG  (4 * MB_)            // 32768 per stage
#define SM_BYTES (3 * STG)        // 98304
#define GEMM_THREADS 128

__device__ __forceinline__ uint32_t swz(int row, int c16) {
    return (uint32_t)(row * 64 + ((c16 ^ ((row >> 1) & 3)) << 4));
}

template <bool RELU, bool WSPL, bool TOWER>
__global__ void __launch_bounds__(GEMM_THREADS, 2)
mma_gemm(const fp16* __restrict__ A0, const fp16* __restrict__ A1,
         const fp16* __restrict__ B0, const fp16* __restrict__ B1,
         const float* __restrict__ bias,
         float* __restrict__ Cf, fp16* __restrict__ C0, fp16* __restrict__ C1,
         const float* __restrict__ w2, float* __restrict__ outT,
         long sA, long sB, long sBias, long sC, long sW2)
{
    extern __shared__ char smem[];
    const uint32_t smbase = smem_u32(smem);
    const int tid = threadIdx.x, wid = tid >> 5, lane = tid & 31;
    const int z = blockIdx.z;
    const long row0 = (long)blockIdx.y * BM;
    const int  n0   = blockIdx.x * BN;

    const fp16* Ag0 = A0 + z * sA + row0 * HDIM;
    const fp16* Ag1 = A1 + z * sA + row0 * HDIM;
    const fp16* Bg0 = B0 + z * sB + (long)n0 * HDIM;
    const fp16* Bg1 = B1 + z * sB + (long)n0 * HDIM;

    const int ldr0 = tid >> 2, ldch = tid & 3;
    auto ldstage = [&](int buf, int kc0) {
        const uint32_t sb = smbase + buf * STG;
#pragma unroll
        for (int i = 0; i < 4; i++) {
            const int r = ldr0 + 32 * i;
            const long g = (long)r * HDIM + kc0 + ldch * 8;
            const uint32_t so = swz(r, ldch);
            cp16(sb + 0 * MB_ + so, Ag0 + g);
            cp16(sb + 1 * MB_ + so, Ag1 + g);
            cp16(sb + 2 * MB_ + so, Bg0 + g);
            cp16(sb + 3 * MB_ + so, Bg1 + g);
        }
    };

    float acc[4][8][4];
#pragma unroll
    for (int mt = 0; mt < 4; mt++)
#pragma unroll
        for (int nt = 0; nt < 8; nt++)
#pragma unroll
            for (int q = 0; q < 4; q++) acc[mt][nt][q] = 0.f;

    const int wm = (wid & 1) * 64;
    const int wn = (wid >> 1) * 64;
    const int grp = lane >> 3, lr = lane & 7;
    const int arow = lr + ((grp & 1) << 3);
    const int ac16 = grp >> 1;
    const int brow = lr + ((grp >> 1) << 3);
    const int bc16 = grp & 1;

    uint32_t abase[4], axm[4], bbase[4], bxm[4];
#pragma unroll
    for (int mt = 0; mt < 4; mt++) {
        const int r = wm + mt * 16 + arow;
        abase[mt] = (uint32_t)(r * 64);
        axm[mt]   = (uint32_t)((r >> 1) & 3);
    }
#pragma unroll
    for (int np = 0; np < 4; np++) {
        const int r = wn + np * 16 + brow;
        bbase[np] = (uint32_t)(r * 64);
        bxm[np]   = (uint32_t)((r >> 1) & 3);
    }

    ldstage(0, 0);           CP_COMMIT();
    ldstage(1, BK);          CP_COMMIT();

    for (int c = 0; c < NKCH; c++) {
        if (c + 1 < NKCH) CP_WAIT1(); else CP_WAIT0();
        __syncthreads();     // chunk c published; buffer (c+2)%3 free

        const uint32_t sb = smbase + (c % 3) * STG;
#pragma unroll
        for (int ks = 0; ks < 2; ks++) {
            uint32_t af[2][4][4];
            uint32_t bfr[2][4][4];
            const uint32_t ka = (uint32_t)(ks * 2 + ac16);
            const uint32_t kb = (uint32_t)(ks * 2 + bc16);
#pragma unroll
            for (int sc = 0; sc < 2; sc++)
#pragma unroll
                for (int mt = 0; mt < 4; mt++)
                    ldsm4(af[sc][mt],
                          sb + sc * MB_ + abase[mt] + ((ka ^ axm[mt]) << 4));
#pragma unroll
            for (int sc = 0; sc < 2; sc++)
#pragma unroll
                for (int np = 0; np < 4; np++)
                    ldsm4(bfr[sc][np],
                          sb + (2 + sc) * MB_ + bbase[np] + ((kb ^ bxm[np]) << 4));

#pragma unroll
            for (int term = 0; term < 3; term++) {
                const int ai = (term == 2) ? 1 : 0;
                const int bi = (term == 1) ? 1 : 0;
#pragma unroll
                for (int np = 0; np < 4; np++)
#pragma unroll
                    for (int mt = 0; mt < 4; mt++) {
                        mma_fp16(acc[mt][2 * np],     af[ai][mt],
                                 bfr[bi][np][0], bfr[bi][np][1]);
                        mma_fp16(acc[mt][2 * np + 1], af[ai][mt],
                                 bfr[bi][np][2], bfr[bi][np][3]);
                    }
            }
        }

        if (c + 2 < NKCH) { ldstage((c + 2) % 3, (c + 2) * BK); CP_COMMIT(); }
    }

    // ------------------------------ epilogue ------------------------------
    const float* biasz = bias + z * sBias;
    const float* w2z   = TOWER ? (w2 + z * sW2) : nullptr;

#pragma unroll
    for (int mt = 0; mt < 4; mt++) {
#pragma unroll
        for (int half = 0; half < 2; half++) {
            const long gr = row0 + wm + mt * 16 + (lane >> 2) + half * 8;
            float p = 0.f;
#pragma unroll
            for (int nt = 0; nt < 8; nt++) {
                const int cc = n0 + wn + nt * 8 + (lane & 3) * 2;
                float v0 = acc[mt][nt][half * 2 + 0] + biasz[cc];
                float v1 = acc[mt][nt][half * 2 + 1] + biasz[cc + 1];
                if (RELU || TOWER) { v0 = fmaxf(v0, 0.f); v1 = fmaxf(v1, 0.f); }
                if (TOWER) {
                    p = fmaf(v0, w2z[cc], p);
                    p = fmaf(v1, w2z[cc + 1], p);
                } else {
                    const long off = z * sC + gr * HDIM + cc;
                    if (Cf != nullptr)
                        *reinterpret_cast<float2*>(&Cf[off]) = make_float2(v0, v1);
                    if (WSPL) {
                        fp16 h0 = __float2half_rn(v0), h1 = __float2half_rn(v1);
                        fp16 l0 = __float2half_rn(v0 - __half2float(h0));
                        fp16 l1 = __float2half_rn(v1 - __half2float(h1));
                        *reinterpret_cast<uint32_t*>(&C0[off]) =
                            (uint32_t)__half_as_ushort(h0) |
                            ((uint32_t)__half_as_ushort(h1) << 16);
                        *reinterpret_cast<uint32_t*>(&C1[off]) =
                            (uint32_t)__half_as_ushort(l0) |
                            ((uint32_t)__half_as_ushort(l1) << 16);
                    }
                }
            }
            if (TOWER) {
                p += __shfl_down_sync(0xffffffffu, p, 2);
                p += __shfl_down_sync(0xffffffffu, p, 1);
                if ((lane & 3) == 0)
                    atomicAdd(&outT[(long)z * NROWS + gr], p);
            }
        }
    }
}

// ===================== fused prep kernel (one launch) ======================
// blockIdx.x dispatch:
//   [0, 8704)   : transpose+split 17 weight units, 64(k)x32(n) tiles,
//                 packed fp16x2 stores (4B coalesced)
//   [+16384)    : cls fp32 -> fp16 hi/lo split (x4 vectorized)
//   [+192)      : out init to tb2[t]
//   [+72)       : wgate transpose [t][h][e] -> [t][e][h]
#define TRN_BLOCKS  (17 * 512)
#define CVT_BLOCKS  ((int)(NH_ / 4 / 256))          // 16384
#define INIT_BLOCKS ((NTASK * NROWS) / 256)         // 192
#define WGT_BLOCKS  ((NTASK * NEXP * HDIM) / 256)   // 72
#define PREP_BLOCKS (TRN_BLOCKS + CVT_BLOCKS + INIT_BLOCKS + WGT_BLOCKS)

__global__ __launch_bounds__(256)
void prep_kernel(const float* __restrict__ fc1w, const float* __restrict__ fc2w,
                 const float* __restrict__ ew1,  const float* __restrict__ ew2,
                 const float* __restrict__ tw1,  fp16* __restrict__ T,
                 const float* __restrict__ cls,  fp16* __restrict__ c0,
                 fp16* __restrict__ c1,
                 const float* __restrict__ tb2,  float* __restrict__ out,
                 const float* __restrict__ wg,   float* __restrict__ wgt)
{
    const int b = blockIdx.x;
    const int tid = threadIdx.x;

    if (b < TRN_BLOCKS) {
        __shared__ float tile[64][33];
        const int z   = b >> 9;             // / 512
        const int rem = b & 511;
        const int k0  = (rem >> 5) << 6;    // 16 k-tiles of 64
        const int n0  = (rem & 31) << 5;    // 32 n-tiles of 32
        const int lane = tid & 31, wrp = tid >> 5;
        const float* src;
        if      (z == 0)  src = fc1w;
        else if (z == 1)  src = fc2w;
        else if (z < 8)   src = ew1 + (long)(z - 2)  * HH_;
        else if (z < 14)  src = ew2 + (long)(z - 8)  * HH_;
        else              src = tw1 + (long)(z - 14) * HH_;
        const long ob = (long)z * 2 * HH_;

        // load 64 k-rows x 32 n-cols, coalesced along n
#pragma unroll
        for (int i = wrp; i < 64; i += 8)
            tile[i][lane] = src[(long)(k0 + i) * HDIM + n0 + lane];
        __syncthreads();

        // store transposed: for each n-row j, lane packs k=2*lane, 2*lane+1
#pragma unroll
        for (int j = wrp; j < 32; j += 8) {
            const float va = tile[2 * lane][j];
            const float vb = tile[2 * lane + 1][j];
            const fp16 ha = __float2half_rn(va);
            const fp16 hb = __float2half_rn(vb);
            const fp16 la = __float2half_rn(va - __half2float(ha));
            const fp16 lb = __float2half_rn(vb - __half2float(hb));
            const long o = ob + (long)(n0 + j) * HDIM + k0 + 2 * lane;
            *reinterpret_cast<uint32_t*>(&T[o]) =
                (uint32_t)__half_as_ushort(ha) | ((uint32_t)__half_as_ushort(hb) << 16);
            *reinterpret_cast<uint32_t*>(&T[o + HH_]) =
                (uint32_t)__half_as_ushort(la) | ((uint32_t)__half_as_ushort(lb) << 16);
        }
    } else if (b < TRN_BLOCKS + CVT_BLOCKS) {
        const long base = ((long)(b - TRN_BLOCKS) * 256 + tid) * 4;
        const float4 v = *reinterpret_cast<const float4*>(cls + base);
        fp16 h0 = __float2half_rn(v.x), h1 = __float2half_rn(v.y);
        fp16 h2 = __float2half_rn(v.z), h3 = __float2half_rn(v.w);
        uint2 hp, lp;
        hp.x = (uint32_t)__half_as_ushort(h0) | ((uint32_t)__half_as_ushort(h1) << 16);
        hp.y = (uint32_t)__half_as_ushort(h2) | ((uint32_t)__half_as_ushort(h3) << 16);
        fp16 l0 = __float2half_rn(v.x - __half2float(h0));
        fp16 l1 = __float2half_rn(v.y - __half2float(h1));
        fp16 l2 = __float2half_rn(v.z - __half2float(h2));
        fp16 l3 = __float2half_rn(v.w - __half2float(h3));
        lp.x = (uint32_t)__half_as_ushort(l0) | ((uint32_t)__half_as_ushort(l1) << 16);
        lp.y = (uint32_t)__half_as_ushort(l2) | ((uint32_t)__half_as_ushort(l3) << 16);
        *reinterpret_cast<uint2*>(c0 + base) = hp;
        *reinterpret_cast<uint2*>(c1 + base) = lp;
    } else if (b < TRN_BLOCKS + CVT_BLOCKS + INIT_BLOCKS) {
        const int i = (b - TRN_BLOCKS - CVT_BLOCKS) * 256 + tid;
        if (i < NTASK * NROWS) out[i] = tb2[i / NROWS];
    } else {
        const int i = (b - TRN_BLOCKS - CVT_BLOCKS - INIT_BLOCKS) * 256 + tid;
        const int t = i / (NEXP * HDIM);
        const int r = i - t * (NEXP * HDIM);
        const int e = r / HDIM;
        const int h = r - e * HDIM;
        wgt[i] = wg[(long)t * HDIM * NEXP + (long)h * NEXP + e];
    }
}

// Gating (R14-proven): one warp per (t, n), block-shared wgate^T tile.
__global__ __launch_bounds__(256)
void gate_kernel(const fp16* __restrict__ h0, const fp16* __restrict__ h1,
                 const float* __restrict__ wgt, float* __restrict__ gates)
{
    __shared__ float ws[NEXP * HDIM];        // 24 KB
    const int tid  = threadIdx.x;
    const int lane = tid & 31;
    const int warp = blockIdx.x * 8 + (tid >> 5);
    const int t = warp / NROWS;
    const int n = warp - t * NROWS;

    {
        const float4* src = reinterpret_cast<const float4*>(wgt + (long)t * NEXP * HDIM);
        float4* dst = reinterpret_cast<float4*>(ws);
#pragma unroll
        for (int i = 0; i < 6; i++)
            dst[tid + 256 * i] = src[tid + 256 * i];
    }
    __syncthreads();

    float acc[NEXP];
#pragma unroll
    for (int e = 0; e < NEXP; e++) acc[e] = 0.f;

    const fp16* hr0 = h0 + (long)n * HDIM;
    const fp16* hr1 = h1 + (long)n * HDIM;

#pragma unroll
    for (int it = 0; it < 8; it++) {
        const int base = it * 128 + lane * 4;
        const uint2 p0 = *reinterpret_cast<const uint2*>(hr0 + base);
        const uint2 p1 = *reinterpret_cast<const uint2*>(hr1 + base);
        float hv[4];
        {
            float2 a0 = __half22float2(*reinterpret_cast<const __half2*>(&p0.x));
            float2 a1 = __half22float2(*reinterpret_cast<const __half2*>(&p0.y));
            float2 b0 = __half22float2(*reinterpret_cast<const __half2*>(&p1.x));
            float2 b1 = __half22float2(*reinterpret_cast<const __half2*>(&p1.y));
            hv[0] = a0.x + b0.x; hv[1] = a0.y + b0.y;
            hv[2] = a1.x + b1.x; hv[3] = a1.y + b1.y;
        }
#pragma unroll
        for (int e = 0; e < NEXP; e++) {
            const float4 w = *reinterpret_cast<const float4*>(&ws[e * HDIM + base]);
            acc[e] = fmaf(hv[0], w.x, acc[e]);
            acc[e] = fmaf(hv[1], w.y, acc[e]);
            acc[e] = fmaf(hv[2], w.z, acc[e]);
            acc[e] = fmaf(hv[3], w.w, acc[e]);
        }
    }
#pragma unroll
    for (int off = 16; off > 0; off >>= 1)
#pragma unroll
        for (int e = 0; e < NEXP; e++)
            acc[e] += __shfl_xor_sync(0xffffffffu, acc[e], off);

    if (lane == 0) {
        float v[NEXP];
#pragma unroll
        for (int e = 0; e < NEXP; e++) v[e] = acc[e];
        int ti[TOPK]; float tv[TOPK];
#pragma unroll
        for (int s = 0; s < TOPK; s++) {
            int bi = 0; float bv = v[0];
#pragma unroll
            for (int e = 1; e < NEXP; e++) if (v[e] > bv) { bv = v[e]; bi = e; }
            ti[s] = bi; tv[s] = bv; v[bi] = -INFINITY;
        }
        const float m = tv[0];
        float w[TOPK], s = 0.f;
#pragma unroll
        for (int k = 0; k < TOPK; k++) { w[k] = expf(tv[k] - m); s += w[k]; }
        const float inv = 1.f / s;
        float gv[NEXP];
#pragma unroll
        for (int e = 0; e < NEXP; e++) gv[e] = 0.f;
#pragma unroll
        for (int k = 0; k < TOPK; k++) gv[ti[k]] = w[k] * inv;
        float* gp = gates + ((long)t * NROWS + n) * NEXP;
#pragma unroll
        for (int e = 0; e < NEXP; e++) gp[e] = gv[e];
    }
}

// Combine (R9-proven, vectorized x4)
__global__ __launch_bounds__(256)
void combine_kernel(const float* __restrict__ eo, const float* __restrict__ gates,
                    fp16* __restrict__ m0, fp16* __restrict__ m1)
{
    const long q = (long)blockIdx.x * blockDim.x + threadIdx.x;
    const long base = q * 4;
    if (base >= NH_) return;
    const int n = (int)(base >> 10);

    float4 v[NEXP];
#pragma unroll
    for (int e = 0; e < NEXP; e++)
        v[e] = *reinterpret_cast<const float4*>(eo + (long)e * NH_ + base);

#pragma unroll
    for (int t = 0; t < NTASK; t++) {
        const float* gp = gates + ((long)t * NROWS + n) * NEXP;
        float g[NEXP];
#pragma unroll
        for (int e = 0; e < NEXP; e++) g[e] = gp[e];
        float r[4] = {0.f, 0.f, 0.f, 0.f};
#pragma unroll
        for (int e = 0; e < NEXP; e++) {
            r[0] = fmaf(g[e], v[e].x, r[0]);
            r[1] = fmaf(g[e], v[e].y, r[1]);
            r[2] = fmaf(g[e], v[e].z, r[2]);
            r[3] = fmaf(g[e], v[e].w, r[3]);
        }
        uint2 hp, lp;
        {
            fp16 h0 = __float2half_rn(r[0]), h1 = __float2half_rn(r[1]);
            fp16 h2 = __float2half_rn(r[2]), h3 = __float2half_rn(r[3]);
            hp.x = (uint32_t)__half_as_ushort(h0) | ((uint32_t)__half_as_ushort(h1) << 16);
            hp.y = (uint32_t)__half_as_ushort(h2) | ((uint32_t)__half_as_ushort(h3) << 16);
            fp16 l0 = __float2half_rn(r[0] - __half2float(h0));
            fp16 l1 = __float2half_rn(r[1] - __half2float(h1));
            fp16 l2 = __float2half_rn(r[2] - __half2float(h2));
            fp16 l3 = __float2half_rn(r[3] - __half2float(h3));
            lp.x = (uint32_t)__half_as_ushort(l0) | ((uint32_t)__half_as_ushort(l1) << 16);
            lp.y = (uint32_t)__half_as_ushort(l2) | ((uint32_t)__half_as_ushort(l3) << 16);
        }
        *reinterpret_cast<uint2*>(m0 + (long)t * NH_ + base) = hp;
        *reinterpret_cast<uint2*>(m1 + (long)t * NH_ + base) = lp;
    }
}

// ================================ launch ===================================
extern "C" void kernel_launch(void* const* d_in, const int* in_sizes, int n_in,
                              void* d_out, int out_size)
{
    const float* cls   = (const float*)d_in[0];
    const float* fc1w  = (const float*)d_in[1];
    const float* fc1b  = (const float*)d_in[2];
    const float* fc2w  = (const float*)d_in[3];
    const float* fc2b  = (const float*)d_in[4];
    const float* wgate = (const float*)d_in[5];
    const float* ew1   = (const float*)d_in[6];
    const float* eb1   = (const float*)d_in[7];
    const float* ew2   = (const float*)d_in[8];
    const float* eb2   = (const float*)d_in[9];
    const float* tw1   = (const float*)d_in[10];
    const float* tb1   = (const float*)d_in[11];
    const float* tw2   = (const float*)d_in[12];
    const float* tb2   = (const float*)d_in[13];
    float* out = (float*)d_out;

    fp16 *clsS, *h1S, *hS, *ehS, *moS, *wt;
    float *eo, *gates, *wgt;
    cudaGetSymbolAddress((void**)&clsS, g_cls);
    cudaGetSymbolAddress((void**)&h1S,  g_h1);
    cudaGetSymbolAddress((void**)&hS,   g_h);
    cudaGetSymbolAddress((void**)&ehS,  g_eh);
    cudaGetSymbolAddress((void**)&eo,   g_eo);
    cudaGetSymbolAddress((void**)&moS,  g_mo);
    cudaGetSymbolAddress((void**)&gates,g_gates);
    cudaGetSymbolAddress((void**)&wt,   g_wt);
    cudaGetSymbolAddress((void**)&wgt,  g_wgt);

    fp16* fc1t = wt;                 // unit 0
    fp16* fc2t = wt + 2 * HH_;       // unit 1
    fp16* ew1t = wt + 4 * HH_;       // units 2..7
    fp16* ew2t = wt + 16 * HH_;      // units 8..13
    fp16* tw1t = wt + 28 * HH_;      // units 14..16

    cudaFuncSetAttribute((const void*)mma_gemm<true,  true,  false>,
                         cudaFuncAttributeMaxDynamicSharedMemorySize, SM_BYTES);
    cudaFuncSetAttribute((const void*)mma_gemm<false, true,  false>,
                         cudaFuncAttributeMaxDynamicSharedMemorySize, SM_BYTES);
    cudaFuncSetAttribute((const void*)mma_gemm<false, false, false>,
                         cudaFuncAttributeMaxDynamicSharedMemorySize, SM_BYTES);
    cudaFuncSetAttribute((const void*)mma_gemm<false, false, true>,
                         cudaFuncAttributeMaxDynamicSharedMemorySize, SM_BYTES);

    const dim3 blk(256);
    const dim3 gblk(GEMM_THREADS);
    const dim3 g1(HDIM / BN, NROWS / BM, 1);
    const dim3 gE(HDIM / BN, NROWS / BM, NEXP);
    const dim3 gT(HDIM / BN, NROWS / BM, NTASK);

    // 0: fused prep — weight transposes + input split + out init + wgate^T
    prep_kernel<<<PREP_BLOCKS, blk>>>(fc1w, fc2w, ew1, ew2, tw1, wt,
                                      cls, clsS, clsS + NH_, tb2, out,
                                      wgate, wgt);

    // 1: fc1 (relu, split out)
    mma_gemm<true, true, false><<<g1, gblk, SM_BYTES>>>(
        clsS, clsS + NH_, fc1t, fc1t + HH_, fc1b,
        nullptr, h1S, h1S + NH_, nullptr, nullptr,
        0, 0, 0, 0, 0);
    // 2: fc2 (split out; gate reads comps)
    mma_gemm<false, true, false><<<g1, gblk, SM_BYTES>>>(
        h1S, h1S + NH_, fc2t, fc2t + HH_, fc2b,
        nullptr, hS, hS + NH_, nullptr, nullptr,
        0, 0, 0, 0, 0);

    // 3: gating (smem-cached wgate^T)
    gate_kernel<<<(NTASK * NROWS) / 8, blk>>>(hS, hS + NH_, wgt, gates);

    // 4: experts layer 1 (relu, split out)
    mma_gemm<true, true, false><<<gE, gblk, SM_BYTES>>>(
        hS, hS + NH_, ew1t, ew1t + HH_, eb1,
        nullptr, ehS, ehS + (long)NEXP * NH_, nullptr, nullptr,
        0, 2 * HH_, HDIM, NH_, 0);
    // 5: experts layer 2 (fp32 out)
    mma_gemm<false, false, false><<<gE, gblk, SM_BYTES>>>(
        ehS, ehS + (long)NEXP * NH_, ew2t, ew2t + HH_, eb2,
        eo, nullptr, nullptr, nullptr, nullptr,
        NH_, 2 * HH_, HDIM, NH_, 0);

    // 6: gate combine (vectorized x4)
    combine_kernel<<<(unsigned)(NH_ / 4 / 256), blk>>>(eo, gates, moS,
                                                       moS + (long)NTASK * NH_);

    // 7: towers (fused relu + tw2 reduction; out pre-initialized by prep)
    mma_gemm<false, false, true><<<gT, gblk, SM_BYTES>>>(
        moS, moS + (long)NTASK * NH_, tw1t, tw1t + HH_, tb1,
        nullptr, nullptr, nullptr, tw2, out,
        NH_, 2 * HH_, HDIM, 0, HDIM);
}

// round 16
// speedup vs baseline: 1.0925x; 1.0081x over previous
#include <cuda_runtime.h>
#include <cuda_fp16.h>
#include <math.h>
#include <stdint.h>

#define NROWS 16384
#define HDIM  1024
#define NEXP  6
#define NTASK 3
#define TOPK  3

typedef __half fp16;
#define NH_ ((long)NROWS * HDIM)          // 16777216
#define HH_ ((long)HDIM * HDIM)           // 1048576

// =============================== Scratch ===================================
__device__ __align__(256) fp16  g_cls[2 * NH_];
__device__ __align__(256) fp16  g_h1 [2 * NH_];
__device__ __align__(256) fp16  g_h  [2 * NH_];
__device__ __align__(256) fp16  g_eh [2 * NEXP * NH_];
__device__ __align__(256) float g_eo [NEXP * NH_];
__device__ __align__(256) fp16  g_mo [2 * NTASK * NH_];
__device__ __align__(256) float g_gates[(long)NTASK * NROWS * NEXP];
__device__ __align__(256) fp16  g_wt [34 * HH_];
__device__ __align__(256) float g_wgt[NTASK * NEXP * HDIM];   // wgate^T [t][e][h]

// =============================== PTX helpers ===============================
__device__ __forceinline__ uint32_t smem_u32(const void* p) {
    uint32_t a;
    asm("{ .reg .u64 t; cvta.to.shared.u64 t, %1; cvt.u32.u64 %0, t; }" : "=r"(a) : "l"(p));
    return a;
}
__device__ __forceinline__ void cp16(uint32_t s, const void* g) {
    asm volatile("cp.async.cg.shared.global [%0], [%1], 16;" :: "r"(s), "l"(g) : "memory");
}
#define CP_COMMIT() asm volatile("cp.async.commit_group;" ::: "memory")
#define CP_WAIT1()  asm volatile("cp.async.wait_group 1;" ::: "memory")
#define CP_WAIT0()  asm volatile("cp.async.wait_group 0;" ::: "memory")

__device__ __forceinline__ void ldsm4(uint32_t (&r)[4], uint32_t addr) {
    asm volatile("ldmatrix.sync.aligned.m8n8.x4.shared.b16 {%0,%1,%2,%3}, [%4];"
                 : "=r"(r[0]), "=r"(r[1]), "=r"(r[2]), "=r"(r[3]) : "r"(addr));
}
__device__ __forceinline__ void mma_fp16(float (&d)[4], const uint32_t (&a)[4],
                                         uint32_t b0, uint32_t b1) {
    asm volatile(
        "mma.sync.aligned.m16n8k16.row.col.f32.f16.f16.f32 "
        "{%0,%1,%2,%3}, {%4,%5,%6,%7}, {%8,%9}, {%0,%1,%2,%3};"
        : "+f"(d[0]), "+f"(d[1]), "+f"(d[2]), "+f"(d[3])
        : "r"(a[0]), "r"(a[1]), "r"(a[2]), "r"(a[3]), "r"(b0), "r"(b1));
}

// ============================ split-fp16 GEMM ==============================
// FROZEN R8/R11 loop: batched ldsm, term-major mma, ldstage AFTER compute.
#define BM 128
#define BN 128
#define BK 32
#define NKCH (HDIM / BK)          // 32
#define MB_  8192                 // one 128x32 fp16 matrix, 64B rows
#define STG  (4 * MB_)            // 32768 per stage
#define SM_BYTES (3 * STG)        // 98304
#define GEMM_THREADS 128

__device__ __forceinline__ uint32_t swz(int row, int c16) {
    return (uint32_t)(row * 64 + ((c16 ^ ((row >> 1) & 3)) << 4));
}

template <bool RELU, bool WSPL, bool TOWER>
__global__ void __launch_bounds__(GEMM_THREADS, 2)
mma_gemm(const fp16* __restrict__ A0, const fp16* __restrict__ A1,
         const fp16* __restrict__ B0, const fp16* __restrict__ B1,
         const float* __restrict__ bias,
         float* __restrict__ Cf, fp16* __restrict__ C0, fp16* __restrict__ C1,
         const float* __restrict__ w2, float* __restrict__ outT,
         long sA, long sB, long sBias, long sC, long sW2)
{
    extern __shared__ char smem[];
    const uint32_t smbase = smem_u32(smem);
    const int tid = threadIdx.x, wid = tid >> 5, lane = tid & 31;
    const int z = blockIdx.z;
    const long row0 = (long)blockIdx.y * BM;
    const int  n0   = blockIdx.x * BN;

    const fp16* Ag0 = A0 + z * sA + row0 * HDIM;
    const fp16* Ag1 = A1 + z * sA + row0 * HDIM;
    const fp16* Bg0 = B0 + z * sB + (long)n0 * HDIM;
    const fp16* Bg1 = B1 + z * sB + (long)n0 * HDIM;

    const int ldr0 = tid >> 2, ldch = tid & 3;
    auto ldstage = [&](int buf, int kc0) {
        const uint32_t sb = smbase + buf * STG;
#pragma unroll
        for (int i = 0; i < 4; i++) {
            const int r = ldr0 + 32 * i;
            const long g = (long)r * HDIM + kc0 + ldch * 8;
            const uint32_t so = swz(r, ldch);
            cp16(sb + 0 * MB_ + so, Ag0 + g);
            cp16(sb + 1 * MB_ + so, Ag1 + g);
            cp16(sb + 2 * MB_ + so, Bg0 + g);
            cp16(sb + 3 * MB_ + so, Bg1 + g);
        }
    };

    float acc[4][8][4];
#pragma unroll
    for (int mt = 0; mt < 4; mt++)
#pragma unroll
        for (int nt = 0; nt < 8; nt++)
#pragma unroll
            for (int q = 0; q < 4; q++) acc[mt][nt][q] = 0.f;

    const int wm = (wid & 1) * 64;
    const int wn = (wid >> 1) * 64;
    const int grp = lane >> 3, lr = lane & 7;
    const int arow = lr + ((grp & 1) << 3);
    const int ac16 = grp >> 1;
    const int brow = lr + ((grp >> 1) << 3);
    const int bc16 = grp & 1;

    uint32_t abase[4], axm[4], bbase[4], bxm[4];
#pragma unroll
    for (int mt = 0; mt < 4; mt++) {
        const int r = wm + mt * 16 + arow;
        abase[mt] = (uint32_t)(r * 64);
        axm[mt]   = (uint32_t)((r >> 1) & 3);
    }
#pragma unroll
    for (int np = 0; np < 4; np++) {
        const int r = wn + np * 16 + brow;
        bbase[np] = (uint32_t)(r * 64);
        bxm[np]   = (uint32_t)((r >> 1) & 3);
    }

    ldstage(0, 0);           CP_COMMIT();
    ldstage(1, BK);          CP_COMMIT();

    for (int c = 0; c < NKCH; c++) {
        if (c + 1 < NKCH) CP_WAIT1(); else CP_WAIT0();
        __syncthreads();     // chunk c published; buffer (c+2)%3 free

        const uint32_t sb = smbase + (c % 3) * STG;
#pragma unroll
        for (int ks = 0; ks < 2; ks++) {
            uint32_t af[2][4][4];
            uint32_t bfr[2][4][4];
            const uint32_t ka = (uint32_t)(ks * 2 + ac16);
            const uint32_t kb = (uint32_t)(ks * 2 + bc16);
#pragma unroll
            for (int sc = 0; sc < 2; sc++)
#pragma unroll
                for (int mt = 0; mt < 4; mt++)
                    ldsm4(af[sc][mt],
                          sb + sc * MB_ + abase[mt] + ((ka ^ axm[mt]) << 4));
#pragma unroll
            for (int sc = 0; sc < 2; sc++)
#pragma unroll
                for (int np = 0; np < 4; np++)
                    ldsm4(bfr[sc][np],
                          sb + (2 + sc) * MB_ + bbase[np] + ((kb ^ bxm[np]) << 4));

#pragma unroll
            for (int term = 0; term < 3; term++) {
                const int ai = (term == 2) ? 1 : 0;
                const int bi = (term == 1) ? 1 : 0;
#pragma unroll
                for (int np = 0; np < 4; np++)
#pragma unroll
                    for (int mt = 0; mt < 4; mt++) {
                        mma_fp16(acc[mt][2 * np],     af[ai][mt],
                                 bfr[bi][np][0], bfr[bi][np][1]);
                        mma_fp16(acc[mt][2 * np + 1], af[ai][mt],
                                 bfr[bi][np][2], bfr[bi][np][3]);
                    }
            }
        }

        if (c + 2 < NKCH) { ldstage((c + 2) % 3, (c + 2) * BK); CP_COMMIT(); }
    }

    // ------------------------------ epilogue ------------------------------
    const float* biasz = bias + z * sBias;
    const float* w2z   = TOWER ? (w2 + z * sW2) : nullptr;

#pragma unroll
    for (int mt = 0; mt < 4; mt++) {
#pragma unroll
        for (int half = 0; half < 2; half++) {
            const long gr = row0 + wm + mt * 16 + (lane >> 2) + half * 8;
            float p = 0.f;
#pragma unroll
            for (int nt = 0; nt < 8; nt++) {
                const int cc = n0 + wn + nt * 8 + (lane & 3) * 2;
                float v0 = acc[mt][nt][half * 2 + 0] + biasz[cc];
                float v1 = acc[mt][nt][half * 2 + 1] + biasz[cc + 1];
                if (RELU || TOWER) { v0 = fmaxf(v0, 0.f); v1 = fmaxf(v1, 0.f); }
                if (TOWER) {
                    p = fmaf(v0, w2z[cc], p);
                    p = fmaf(v1, w2z[cc + 1], p);
                } else {
                    const long off = z * sC + gr * HDIM + cc;
                    if (Cf != nullptr)
                        *reinterpret_cast<float2*>(&Cf[off]) = make_float2(v0, v1);
                    if (WSPL) {
                        fp16 h0 = __float2half_rn(v0), h1 = __float2half_rn(v1);
                        fp16 l0 = __float2half_rn(v0 - __half2float(h0));
                        fp16 l1 = __float2half_rn(v1 - __half2float(h1));
                        *reinterpret_cast<uint32_t*>(&C0[off]) =
                            (uint32_t)__half_as_ushort(h0) |
                            ((uint32_t)__half_as_ushort(h1) << 16);
                        *reinterpret_cast<uint32_t*>(&C1[off]) =
                            (uint32_t)__half_as_ushort(l0) |
                            ((uint32_t)__half_as_ushort(l1) << 16);
                    }
                }
            }
            if (TOWER) {
                p += __shfl_down_sync(0xffffffffu, p, 2);
                p += __shfl_down_sync(0xffffffffu, p, 1);
                if ((lane & 3) == 0)
                    atomicAdd(&outT[(long)z * NROWS + gr], p);
            }
        }
    }
}

// ==================== prep kernels (main path + side path) =================
// Shared transpose helper: transpose+split weight unit z (64k x 32n tiles).
__device__ __forceinline__ void transpose_tile(const float* __restrict__ src,
                                               fp16* __restrict__ T, int z,
                                               int rem, int tid)
{
    __shared__ float tile[64][33];
    const int k0 = (rem >> 5) << 6;
    const int n0 = (rem & 31) << 5;
    const int lane = tid & 31, wrp = tid >> 5;
    const long ob = (long)z * 2 * HH_;
#pragma unroll
    for (int i = wrp; i < 64; i += 8)
        tile[i][lane] = src[(long)(k0 + i) * HDIM + n0 + lane];
    __syncthreads();
#pragma unroll
    for (int j = wrp; j < 32; j += 8) {
        const float va = tile[2 * lane][j];
        const float vb = tile[2 * lane + 1][j];
        const fp16 ha = __float2half_rn(va);
        const fp16 hb = __float2half_rn(vb);
        const fp16 la = __float2half_rn(va - __half2float(ha));
        const fp16 lb = __float2half_rn(vb - __half2float(hb));
        const long o = ob + (long)(n0 + j) * HDIM + k0 + 2 * lane;
        *reinterpret_cast<uint32_t*>(&T[o]) =
            (uint32_t)__half_as_ushort(ha) | ((uint32_t)__half_as_ushort(hb) << 16);
        *reinterpret_cast<uint32_t*>(&T[o + HH_]) =
            (uint32_t)__half_as_ushort(la) | ((uint32_t)__half_as_ushort(lb) << 16);
    }
}

// Main-path prep: fc1/fc2 transposes (2*512) + cls split (16384).
#define PMAIN_TRN  (2 * 512)
#define PMAIN_CVT  ((int)(NH_ / 4 / 256))
#define PMAIN_BLOCKS (PMAIN_TRN + PMAIN_CVT)

__global__ __launch_bounds__(256)
void prep_main(const float* __restrict__ fc1w, const float* __restrict__ fc2w,
               fp16* __restrict__ T,
               const float* __restrict__ cls, fp16* __restrict__ c0,
               fp16* __restrict__ c1)
{
    const int b = blockIdx.x, tid = threadIdx.x;
    if (b < PMAIN_TRN) {
        const int z = b >> 9;
        transpose_tile(z == 0 ? fc1w : fc2w, T, z, b & 511, tid);
    } else {
        const long base = ((long)(b - PMAIN_TRN) * 256 + tid) * 4;
        const float4 v = *reinterpret_cast<const float4*>(cls + base);
        fp16 h0 = __float2half_rn(v.x), h1 = __float2half_rn(v.y);
        fp16 h2 = __float2half_rn(v.z), h3 = __float2half_rn(v.w);
        uint2 hp, lp;
        hp.x = (uint32_t)__half_as_ushort(h0) | ((uint32_t)__half_as_ushort(h1) << 16);
        hp.y = (uint32_t)__half_as_ushort(h2) | ((uint32_t)__half_as_ushort(h3) << 16);
        fp16 l0 = __float2half_rn(v.x - __half2float(h0));
        fp16 l1 = __float2half_rn(v.y - __half2float(h1));
        fp16 l2 = __float2half_rn(v.z - __half2float(h2));
        fp16 l3 = __float2half_rn(v.w - __half2float(h3));
        lp.x = (uint32_t)__half_as_ushort(l0) | ((uint32_t)__half_as_ushort(l1) << 16);
        lp.y = (uint32_t)__half_as_ushort(l2) | ((uint32_t)__half_as_ushort(l3) << 16);
        *reinterpret_cast<uint2*>(c0 + base) = hp;
        *reinterpret_cast<uint2*>(c1 + base) = lp;
    }
}

// Side-path prep: ew1/ew2/tw1 transposes (15*512) + out init (192) + wgt (72).
#define PSIDE_TRN  (15 * 512)
#define PSIDE_INIT ((NTASK * NROWS) / 256)
#define PSIDE_WGT  ((NTASK * NEXP * HDIM) / 256)
#define PSIDE_BLOCKS (PSIDE_TRN + PSIDE_INIT + PSIDE_WGT)

__global__ __launch_bounds__(256)
void prep_side(const float* __restrict__ ew1, const float* __restrict__ ew2,
               const float* __restrict__ tw1, fp16* __restrict__ T,
               const float* __restrict__ tb2, float* __restrict__ out,
               const float* __restrict__ wg,  float* __restrict__ wgt)
{
    const int b = blockIdx.x, tid = threadIdx.x;
    if (b < PSIDE_TRN) {
        const int u = b >> 9;            // 0..14
        const int z = u + 2;             // dest unit 2..16
        const float* src;
        if      (u < 6)  src = ew1 + (long)u * HH_;
        else if (u < 12) src = ew2 + (long)(u - 6) * HH_;
        else             src = tw1 + (long)(u - 12) * HH_;
        transpose_tile(src, T, z, b & 511, tid);
    } else if (b < PSIDE_TRN + PSIDE_INIT) {
        const int i = (b - PSIDE_TRN) * 256 + tid;
        if (i < NTASK * NROWS) out[i] = tb2[i / NROWS];
    } else {
        const int i = (b - PSIDE_TRN - PSIDE_INIT) * 256 + tid;
        const int t = i / (NEXP * HDIM);
        const int r = i - t * (NEXP * HDIM);
        const int e = r / HDIM;
        const int h = r - e * HDIM;
        wgt[i] = wg[(long)t * HDIM * NEXP + (long)h * NEXP + e];
    }
}

// Gating (R14-proven): one warp per (t, n), block-shared wgate^T tile.
__global__ __launch_bounds__(256)
void gate_kernel(const fp16* __restrict__ h0, const fp16* __restrict__ h1,
                 const float* __restrict__ wgt, float* __restrict__ gates)
{
    __shared__ float ws[NEXP * HDIM];        // 24 KB
    const int tid  = threadIdx.x;
    const int lane = tid & 31;
    const int warp = blockIdx.x * 8 + (tid >> 5);
    const int t = warp / NROWS;
    const int n = warp - t * NROWS;

    {
        const float4* src = reinterpret_cast<const float4*>(wgt + (long)t * NEXP * HDIM);
        float4* dst = reinterpret_cast<float4*>(ws);
#pragma unroll
        for (int i = 0; i < 6; i++)
            dst[tid + 256 * i] = src[tid + 256 * i];
    }
    __syncthreads();

    float acc[NEXP];
#pragma unroll
    for (int e = 0; e < NEXP; e++) acc[e] = 0.f;

    const fp16* hr0 = h0 + (long)n * HDIM;
    const fp16* hr1 = h1 + (long)n * HDIM;

#pragma unroll
    for (int it = 0; it < 8; it++) {
        const int base = it * 128 + lane * 4;
        const uint2 p0 = *reinterpret_cast<const uint2*>(hr0 + base);
        const uint2 p1 = *reinterpret_cast<const uint2*>(hr1 + base);
        float hv[4];
        {
            float2 a0 = __half22float2(*reinterpret_cast<const __half2*>(&p0.x));
            float2 a1 = __half22float2(*reinterpret_cast<const __half2*>(&p0.y));
            float2 b0 = __half22float2(*reinterpret_cast<const __half2*>(&p1.x));
            float2 b1 = __half22float2(*reinterpret_cast<const __half2*>(&p1.y));
            hv[0] = a0.x + b0.x; hv[1] = a0.y + b0.y;
            hv[2] = a1.x + b1.x; hv[3] = a1.y + b1.y;
        }
#pragma unroll
        for (int e = 0; e < NEXP; e++) {
            const float4 w = *reinterpret_cast<const float4*>(&ws[e * HDIM + base]);
            acc[e] = fmaf(hv[0], w.x, acc[e]);
            acc[e] = fmaf(hv[1], w.y, acc[e]);
            acc[e] = fmaf(hv[2], w.z, acc[e]);
            acc[e] = fmaf(hv[3], w.w, acc[e]);
        }
    }
#pragma unroll
    for (int off = 16; off > 0; off >>= 1)
#pragma unroll
        for (int e = 0; e < NEXP; e++)
            acc[e] += __shfl_xor_sync(0xffffffffu, acc[e], off);

    if (lane == 0) {
        float v[NEXP];
#pragma unroll
        for (int e = 0; e < NEXP; e++) v[e] = acc[e];
        int ti[TOPK]; float tv[TOPK];
#pragma unroll
        for (int s = 0; s < TOPK; s++) {
            int bi = 0; float bv = v[0];
#pragma unroll
            for (int e = 1; e < NEXP; e++) if (v[e] > bv) { bv = v[e]; bi = e; }
            ti[s] = bi; tv[s] = bv; v[bi] = -INFINITY;
        }
        const float m = tv[0];
        float w[TOPK], s = 0.f;
#pragma unroll
        for (int k = 0; k < TOPK; k++) { w[k] = expf(tv[k] - m); s += w[k]; }
        const float inv = 1.f / s;
        float gv[NEXP];
#pragma unroll
        for (int e = 0; e < NEXP; e++) gv[e] = 0.f;
#pragma unroll
        for (int k = 0; k < TOPK; k++) gv[ti[k]] = w[k] * inv;
        float* gp = gates + ((long)t * NROWS + n) * NEXP;
#pragma unroll
        for (int e = 0; e < NEXP; e++) gp[e] = gv[e];
    }
}

// Combine (R9-proven, vectorized x4)
__global__ __launch_bounds__(256)
void combine_kernel(const float* __restrict__ eo, const float* __restrict__ gates,
                    fp16* __restrict__ m0, fp16* __restrict__ m1)
{
    const long q = (long)blockIdx.x * blockDim.x + threadIdx.x;
    const long base = q * 4;
    if (base >= NH_) return;
    const int n = (int)(base >> 10);

    float4 v[NEXP];
#pragma unroll
    for (int e = 0; e < NEXP; e++)
        v[e] = *reinterpret_cast<const float4*>(eo + (long)e * NH_ + base);

#pragma unroll
    for (int t = 0; t < NTASK; t++) {
        const float* gp = gates + ((long)t * NROWS + n) * NEXP;
        float g[NEXP];
#pragma unroll
        for (int e = 0; e < NEXP; e++) g[e] = gp[e];
        float r[4] = {0.f, 0.f, 0.f, 0.f};
#pragma unroll
        for (int e = 0; e < NEXP; e++) {
            r[0] = fmaf(g[e], v[e].x, r[0]);
            r[1] = fmaf(g[e], v[e].y, r[1]);
            r[2] = fmaf(g[e], v[e].z, r[2]);
            r[3] = fmaf(g[e], v[e].w, r[3]);
        }
        uint2 hp, lp;
        {
            fp16 h0 = __float2half_rn(r[0]), h1 = __float2half_rn(r[1]);
            fp16 h2 = __float2half_rn(r[2]), h3 = __float2half_rn(r[3]);
            hp.x = (uint32_t)__half_as_ushort(h0) | ((uint32_t)__half_as_ushort(h1) << 16);
            hp.y = (uint32_t)__half_as_ushort(h2) | ((uint32_t)__half_as_ushort(h3) << 16);
            fp16 l0 = __float2half_rn(r[0] - __half2float(h0));
            fp16 l1 = __float2half_rn(r[1] - __half2float(h1));
            fp16 l2 = __float2half_rn(r[2] - __half2float(h2));
            fp16 l3 = __float2half_rn(r[3] - __half2float(h3));
            lp.x = (uint32_t)__half_as_ushort(l0) | ((uint32_t)__half_as_ushort(l1) << 16);
            lp.y = (uint32_t)__half_as_ushort(l2) | ((uint32_t)__half_as_ushort(l3) << 16);
        }
        *reinterpret_cast<uint2*>(m0 + (long)t * NH_ + base) = hp;
        *reinterpret_cast<uint2*>(m1 + (long)t * NH_ + base) = lp;
    }
}

// ================================ launch ===================================
extern "C" void kernel_launch(void* const* d_in, const int* in_sizes, int n_in,
                              void* d_out, int out_size)
{
    const float* cls   = (const float*)d_in[0];
    const float* fc1w  = (const float*)d_in[1];
    const float* fc1b  = (const float*)d_in[2];
    const float* fc2w  = (const float*)d_in[3];
    const float* fc2b  = (const float*)d_in[4];
    const float* wgate = (const float*)d_in[5];
    const float* ew1   = (const float*)d_in[6];
    const float* eb1   = (const float*)d_in[7];
    const float* ew2   = (const float*)d_in[8];
    const float* eb2   = (const float*)d_in[9];
    const float* tw1   = (const float*)d_in[10];
    const float* tb1   = (const float*)d_in[11];
    const float* tw2   = (const float*)d_in[12];
    const float* tb2   = (const float*)d_in[13];
    float* out = (float*)d_out;

    fp16 *clsS, *h1S, *hS, *ehS, *moS, *wt;
    float *eo, *gates, *wgt;
    cudaGetSymbolAddress((void**)&clsS, g_cls);
    cudaGetSymbolAddress((void**)&h1S,  g_h1);
    cudaGetSymbolAddress((void**)&hS,   g_h);
    cudaGetSymbolAddress((void**)&ehS,  g_eh);
    cudaGetSymbolAddress((void**)&eo,   g_eo);
    cudaGetSymbolAddress((void**)&moS,  g_mo);
    cudaGetSymbolAddress((void**)&gates,g_gates);
    cudaGetSymbolAddress((void**)&wt,   g_wt);
    cudaGetSymbolAddress((void**)&wgt,  g_wgt);

    fp16* fc1t = wt;                 // unit 0
    fp16* fc2t = wt + 2 * HH_;       // unit 1
    fp16* ew1t = wt + 4 * HH_;       // units 2..7
    fp16* ew2t = wt + 16 * HH_;      // units 8..13
    fp16* tw1t = wt + 28 * HH_;      // units 14..16

    cudaFuncSetAttribute((const void*)mma_gemm<true,  true,  false>,
                         cudaFuncAttributeMaxDynamicSharedMemorySize, SM_BYTES);
    cudaFuncSetAttribute((const void*)mma_gemm<false, true,  false>,
                         cudaFuncAttributeMaxDynamicSharedMemorySize, SM_BYTES);
    cudaFuncSetAttribute((const void*)mma_gemm<false, false, false>,
                         cudaFuncAttributeMaxDynamicSharedMemorySize, SM_BYTES);
    cudaFuncSetAttribute((const void*)mma_gemm<false, false, true>,
                         cudaFuncAttributeMaxDynamicSharedMemorySize, SM_BYTES);

    // Fork/join resources: created per call (kernel_launch runs only a few
    // times — correctness + capture), never destroyed; no device-mem alloc.
    cudaStream_t side;
    cudaEvent_t evFork, evPrep, evFc2, evGate;
    cudaStreamCreateWithFlags(&side, cudaStreamNonBlocking);
    cudaEventCreateWithFlags(&evFork, cudaEventDisableTiming);
    cudaEventCreateWithFlags(&evPrep, cudaEventDisableTiming);
    cudaEventCreateWithFlags(&evFc2,  cudaEventDisableTiming);
    cudaEventCreateWithFlags(&evGate, cudaEventDisableTiming);

    const dim3 blk(256);
    const dim3 gblk(GEMM_THREADS);
    const dim3 g1(HDIM / BN, NROWS / BM, 1);
    const dim3 gE(HDIM / BN, NROWS / BM, NEXP);
    const dim3 gT(HDIM / BN, NROWS / BM, NTASK);

    // fork side path
    cudaEventRecord(evFork, 0);
    cudaStreamWaitEvent(side, evFork, 0);
    prep_side<<<PSIDE_BLOCKS, blk, 0, side>>>(ew1, ew2, tw1, wt, tb2, out,
                                              wgate, wgt);
    cudaEventRecord(evPrep, side);

    // main path: prep_main -> fc1 -> fc2
    prep_main<<<PMAIN_BLOCKS, blk>>>(fc1w, fc2w, wt, cls, clsS, clsS + NH_);
    mma_gemm<true, true, false><<<g1, gblk, SM_BYTES>>>(
        clsS, clsS + NH_, fc1t, fc1t + HH_, fc1b,
        nullptr, h1S, h1S + NH_, nullptr, nullptr,
        0, 0, 0, 0, 0);
    mma_gemm<false, true, false><<<g1, gblk, SM_BYTES>>>(
        h1S, h1S + NH_, fc2t, fc2t + HH_, fc2b,
        nullptr, hS, hS + NH_, nullptr, nullptr,
        0, 0, 0, 0, 0);
    cudaEventRecord(evFc2, 0);

    // side path: gate (needs hS + wgt) overlaps expert GEMMs
    cudaStreamWaitEvent(side, evFc2, 0);
    gate_kernel<<<(NTASK * NROWS) / 8, blk, 0, side>>>(hS, hS + NH_, wgt, gates);
    cudaEventRecord(evGate, side);

    // main path: experts (need side prep done)
    cudaStreamWaitEvent(0, evPrep, 0);
    mma_gemm<true, true, false><<<gE, gblk, SM_BYTES>>>(
        hS, hS + NH_, ew1t, ew1t + HH_, eb1,
        nullptr, ehS, ehS + (long)NEXP * NH_, nullptr, nullptr,
        0, 2 * HH_, HDIM, NH_, 0);
    mma_gemm<false, false, false><<<gE, gblk, SM_BYTES>>>(
        ehS, ehS + (long)NEXP * NH_, ew2t, ew2t + HH_, eb2,
        eo, nullptr, nullptr, nullptr, nullptr,
        NH_, 2 * HH_, HDIM, NH_, 0);

    // join: combine needs gates
    cudaStreamWaitEvent(0, evGate, 0);
    combine_kernel<<<(unsigned)(NH_ / 4 / 256), blk>>>(eo, gates, moS,
                                                       moS + (long)NTASK * NH_);

    // towers (out pre-initialized by prep_side)
    mma_gemm<false, false, true><<<gT, gblk, SM_BYTES>>>(
        moS, moS + (long)NTASK * NH_, tw1t, tw1t + HH_, tb1,
        nullptr, nullptr, nullptr, tw2, out,
        NH_, 2 * HH_, HDIM, 0, HDIM);
}